// round 2
// baseline (speedup 1.0000x reference)
#include <cuda_runtime.h>
#include <math.h>

#define NB      2048
#define EXPR    8000
#define H1      1024
#define H2      100
#define M_TOT   4096
#define DD      78
#define DN      200
#define NPG     64
#define EPG     128
#define NG      2048
#define ET_TOT  262144
#define KTOP    52

__device__ float g_h1[M_TOT * H1];     // 16.8 MB scratch
__device__ float g_dx[NG * 400];       // 3.3 MB scratch

// ============================================================================
// GEMM1: h1 = relu(((x*bn0_s + bn0_t) @ W1^T + b1)*bn1_s + bn1_t)
// M=4096 (x1 rows 0..2047, x2 rows 2048..4095), N=1024, K=8000
// ============================================================================
#define G1_BM 128
#define G1_BN 64
#define G1_BK 16
#define G1_PAD 17

__global__ __launch_bounds__(256) void gemm1_kernel(
    const float* __restrict__ x1, const float* __restrict__ x2,
    const float* __restrict__ W1, const float* __restrict__ b1,
    const float* __restrict__ bn0_s, const float* __restrict__ bn0_t,
    const float* __restrict__ bn1_s, const float* __restrict__ bn1_t)
{
    __shared__ float As[G1_BM * G1_PAD];
    __shared__ float Bs[G1_BN * G1_PAD];

    const int tid = threadIdx.x;
    const int tx = tid & 15;          // 0..15 -> 4 cols each
    const int ty = tid >> 4;          // 0..15 -> 8 rows each
    const int brow = blockIdx.y;      // 0..31
    const int bcol = blockIdx.x;      // 0..15

    const float* X = (brow < 16) ? x1 : x2;
    const int rowbase = (brow & 15) * G1_BM;
    const int colbase = bcol * G1_BN;

    // A tile: 128x16 = 512 float4, 2 per thread. B tile: 64x16 = 256 float4, 1 per thread.
    const int ra0 = tid >> 2,         ca0 = (tid & 3) * 4;
    const int ra1 = (tid + 256) >> 2, ca1 = ((tid + 256) & 3) * 4;
    const int rb  = tid >> 2,         cb  = (tid & 3) * 4;

    const float* pA0 = X + (size_t)(rowbase + ra0) * EXPR + ca0;
    const float* pA1 = X + (size_t)(rowbase + ra1) * EXPR + ca1;
    const float* pB  = W1 + (size_t)(colbase + rb) * EXPR + cb;

    float4 pa0, pa1, pb4, s0, t0, s1, t1;

    // initial load
    {
        pa0 = *(const float4*)(pA0);
        pa1 = *(const float4*)(pA1);
        pb4 = *(const float4*)(pB);
        s0 = *(const float4*)&bn0_s[ca0];  t0 = *(const float4*)&bn0_t[ca0];
        s1 = *(const float4*)&bn0_s[ca1];  t1 = *(const float4*)&bn0_t[ca1];
    }
    // store tile 0
    As[ra0*G1_PAD + ca0 + 0] = pa0.x*s0.x + t0.x;
    As[ra0*G1_PAD + ca0 + 1] = pa0.y*s0.y + t0.y;
    As[ra0*G1_PAD + ca0 + 2] = pa0.z*s0.z + t0.z;
    As[ra0*G1_PAD + ca0 + 3] = pa0.w*s0.w + t0.w;
    As[ra1*G1_PAD + ca1 + 0] = pa1.x*s1.x + t1.x;
    As[ra1*G1_PAD + ca1 + 1] = pa1.y*s1.y + t1.y;
    As[ra1*G1_PAD + ca1 + 2] = pa1.z*s1.z + t1.z;
    As[ra1*G1_PAD + ca1 + 3] = pa1.w*s1.w + t1.w;
    Bs[rb*G1_PAD + cb + 0] = pb4.x;
    Bs[rb*G1_PAD + cb + 1] = pb4.y;
    Bs[rb*G1_PAD + cb + 2] = pb4.z;
    Bs[rb*G1_PAD + cb + 3] = pb4.w;
    __syncthreads();

    float acc[8][4];
    #pragma unroll
    for (int i = 0; i < 8; ++i)
        #pragma unroll
        for (int j = 0; j < 4; ++j) acc[i][j] = 0.f;

    const int NT_K = EXPR / G1_BK;  // 500
    for (int kt = 0; kt < NT_K; ++kt) {
        const bool has = (kt + 1) < NT_K;
        const int k0n = (kt + 1) * G1_BK;
        if (has) {
            pa0 = *(const float4*)(pA0 + k0n);
            pa1 = *(const float4*)(pA1 + k0n);
            pb4 = *(const float4*)(pB + k0n);
            s0 = *(const float4*)&bn0_s[k0n + ca0];  t0 = *(const float4*)&bn0_t[k0n + ca0];
            s1 = *(const float4*)&bn0_s[k0n + ca1];  t1 = *(const float4*)&bn0_t[k0n + ca1];
        }
        #pragma unroll
        for (int kk = 0; kk < G1_BK; ++kk) {
            float a[8], bb[4];
            #pragma unroll
            for (int i = 0; i < 8; ++i) a[i] = As[(ty*8 + i)*G1_PAD + kk];
            #pragma unroll
            for (int j = 0; j < 4; ++j) bb[j] = Bs[(tx*4 + j)*G1_PAD + kk];
            #pragma unroll
            for (int i = 0; i < 8; ++i)
                #pragma unroll
                for (int j = 0; j < 4; ++j) acc[i][j] += a[i] * bb[j];
        }
        __syncthreads();
        if (has) {
            As[ra0*G1_PAD + ca0 + 0] = pa0.x*s0.x + t0.x;
            As[ra0*G1_PAD + ca0 + 1] = pa0.y*s0.y + t0.y;
            As[ra0*G1_PAD + ca0 + 2] = pa0.z*s0.z + t0.z;
            As[ra0*G1_PAD + ca0 + 3] = pa0.w*s0.w + t0.w;
            As[ra1*G1_PAD + ca1 + 0] = pa1.x*s1.x + t1.x;
            As[ra1*G1_PAD + ca1 + 1] = pa1.y*s1.y + t1.y;
            As[ra1*G1_PAD + ca1 + 2] = pa1.z*s1.z + t1.z;
            As[ra1*G1_PAD + ca1 + 3] = pa1.w*s1.w + t1.w;
            Bs[rb*G1_PAD + cb + 0] = pb4.x;
            Bs[rb*G1_PAD + cb + 1] = pb4.y;
            Bs[rb*G1_PAD + cb + 2] = pb4.z;
            Bs[rb*G1_PAD + cb + 3] = pb4.w;
            __syncthreads();
        }
    }

    // epilogue: relu(acc*bn1_s + b1*bn1_s + bn1_t)
    float alpha[4], beta[4];
    #pragma unroll
    for (int j = 0; j < 4; ++j) {
        int n = colbase + tx*4 + j;
        alpha[j] = bn1_s[n];
        beta[j]  = b1[n]*alpha[j] + bn1_t[n];
    }
    #pragma unroll
    for (int i = 0; i < 8; ++i) {
        int m = brow*G1_BM + ty*8 + i;
        float4 v;
        v.x = fmaxf(acc[i][0]*alpha[0] + beta[0], 0.f);
        v.y = fmaxf(acc[i][1]*alpha[1] + beta[1], 0.f);
        v.z = fmaxf(acc[i][2]*alpha[2] + beta[2], 0.f);
        v.w = fmaxf(acc[i][3]*alpha[3] + beta[3], 0.f);
        *(float4*)&g_h1[(size_t)m*H1 + colbase + tx*4] = v;
    }
}

// ============================================================================
// GEMM2: f = relu((h1 @ W2^T + b2)*bn2_s + bn2_t); rows<2048 -> f1, else f2
// M=4096, K=1024, N=100.  Block: 32 rows. Thread: 2 rows x 7 cols.
// ============================================================================
#define G2_BK 16

__global__ __launch_bounds__(256) void gemm2_kernel(
    const float* __restrict__ W2, const float* __restrict__ b2,
    const float* __restrict__ bn2_s, const float* __restrict__ bn2_t,
    float* __restrict__ out)
{
    __shared__ float As[32 * G2_BK];
    __shared__ float Bs[112 * 17];

    const int tid = threadIdx.x;
    const int tx = tid & 15;     // col group
    const int ty = tid >> 4;     // row base
    const int m0 = blockIdx.x * 32;

    const int rowA = tid >> 3, c2 = (tid & 7) * 2;
    const float* pA = g_h1 + (size_t)(m0 + rowA) * H1 + c2;

    float2 aPre;
    float  bPre[7];

    // load tile 0
    aPre = *(const float2*)(pA);
    #pragma unroll
    for (int it = 0; it < 7; ++it) {
        int i = tid + it*256;
        if (i < 1600) bPre[it] = W2[(size_t)(i/16) * H1 + (i & 15)];
    }
    As[rowA*G2_BK + c2] = aPre.x;  As[rowA*G2_BK + c2 + 1] = aPre.y;
    #pragma unroll
    for (int it = 0; it < 7; ++it) {
        int i = tid + it*256;
        if (i < 1600) Bs[(i/16)*17 + (i & 15)] = bPre[it];
    }
    __syncthreads();

    float acc0[7], acc1[7];
    #pragma unroll
    for (int j = 0; j < 7; ++j) { acc0[j] = 0.f; acc1[j] = 0.f; }

    const int NT_K = H1 / G2_BK;  // 64
    for (int kt = 0; kt < NT_K; ++kt) {
        const bool has = (kt + 1) < NT_K;
        const int k0n = (kt + 1) * G2_BK;
        if (has) {
            aPre = *(const float2*)(pA + k0n);
            #pragma unroll
            for (int it = 0; it < 7; ++it) {
                int i = tid + it*256;
                if (i < 1600) bPre[it] = W2[(size_t)(i/16) * H1 + k0n + (i & 15)];
            }
        }
        #pragma unroll
        for (int kk = 0; kk < G2_BK; ++kk) {
            float a0 = As[ty*G2_BK + kk];
            float a1 = As[(ty + 16)*G2_BK + kk];
            #pragma unroll
            for (int j = 0; j < 7; ++j) {
                float bv = Bs[(tx + 16*j)*17 + kk];
                acc0[j] += a0 * bv;
                acc1[j] += a1 * bv;
            }
        }
        __syncthreads();
        if (has) {
            As[rowA*G2_BK + c2] = aPre.x;  As[rowA*G2_BK + c2 + 1] = aPre.y;
            #pragma unroll
            for (int it = 0; it < 7; ++it) {
                int i = tid + it*256;
                if (i < 1600) Bs[(i/16)*17 + (i & 15)] = bPre[it];
            }
            __syncthreads();
        }
    }

    #pragma unroll
    for (int j = 0; j < 7; ++j) {
        int n = tx + 16*j;
        if (n >= H2) continue;
        float al = bn2_s[n];
        float be = b2[n]*al + bn2_t[n];
        int m_a = m0 + ty, m_b = m0 + ty + 16;
        float va = fmaxf(acc0[j]*al + be, 0.f);
        float vb = fmaxf(acc1[j]*al + be, 0.f);
        size_t oa = (m_a < NB) ? ((size_t)m_a*H2 + n) : ((size_t)NB*H2 + (size_t)(m_a - NB)*H2 + n);
        size_t ob = (m_b < NB) ? ((size_t)m_b*H2 + n) : ((size_t)NB*H2 + (size_t)(m_b - NB)*H2 + n);
        out[oa] = va;
        out[ob] = vb;
    }
}

// ============================================================================
// Drug encoder: one CTA per graph. Everything in SMEM.
// ============================================================================
#define XPAD 79
#define HPAD 201
#define SM_WREL   0
#define SM_WROOT  (SM_WREL  + DD*DN)         // 15600
#define SM_XS     (SM_WROOT + DD*DN)         // 15600
#define SM_AGG    (SM_XS    + NPG*XPAD)      // 5056
#define SM_H      (SM_AGG   + NPG*XPAD)      // 5056
#define SM_TW     (SM_H     + NPG*HPAD)      // 12864
#define SM_SCORE  (SM_TW    + DN)            // 200
#define SM_RED    (SM_SCORE + NPG)           // 64
#define SM_FLOATS (SM_RED   + 1)
#define SM_DRUG_BYTES (SM_FLOATS*4 + (NPG + 2*EPG)*4)

__global__ __launch_bounds__(256) void drug_kernel(
    const float* __restrict__ drug_x, const int* __restrict__ edge_index,
    const float* __restrict__ Wrel, const float* __restrict__ brel,
    const float* __restrict__ Wroot,
    const float* __restrict__ bnd_s, const float* __restrict__ bnd_t,
    const float* __restrict__ topk_w)
{
    extern __shared__ float sm[];
    float* WrelT  = sm + SM_WREL;    // [d][c] transposed
    float* WrootT = sm + SM_WROOT;
    float* xs     = sm + SM_XS;      // [n][79]
    float* agg    = sm + SM_AGG;
    float* hsh    = sm + SM_H;       // [n][201]
    float* tw     = sm + SM_TW;
    float* score  = sm + SM_SCORE;
    float* red    = sm + SM_RED;
    int* flag = (int*)(sm + SM_FLOATS);
    int* es   = flag + NPG;
    int* ed   = es + EPG;

    const int g = blockIdx.x;
    const int tid = threadIdx.x;

    // stage weights transposed (float2-vectorized broadcast reads later)
    for (int i = tid; i < DN*DD; i += 256) {
        int c = i / DD, d = i % DD;
        WrelT[d*DN + c]  = Wrel[i];
        WrootT[d*DN + c] = Wroot[i];
    }
    for (int i = tid; i < NPG*DD; i += 256) {
        int n = i / DD, d = i % DD;
        xs[n*XPAD + d]  = drug_x[(size_t)(g*NPG + n)*DD + d];
        agg[n*XPAD + d] = 0.f;
    }
    if (tid < DN) tw[tid] = topk_w[tid];
    if (tid < EPG) {
        es[tid] = edge_index[g*EPG + tid] - g*NPG;
        ed[tid] = edge_index[ET_TOT + g*EPG + tid] - g*NPG;
    }
    if (tid == 0) red[0] = 0.f;
    __syncthreads();

    if (tid < DN) atomicAdd(&red[0], tw[tid]*tw[tid]);
    // edge aggregation: one thread per feature dim, sequential over edges (no races)
    if (tid < DD) {
        const int d = tid;
        for (int e = 0; e < EPG; ++e)
            agg[ed[e]*XPAD + d] += xs[es[e]*XPAD + d];
    }
    __syncthreads();

    // node GEMM: h[n][c] = relu((agg.Wrel + x.Wroot + brel)*s + t)
    const int n = tid & 63;
    const int txg = tid >> 6;           // 0..3
    const int cbase = txg * 50;
    float acc[50];
    #pragma unroll
    for (int j = 0; j < 50; ++j) acc[j] = 0.f;

    const float* ap = &agg[n*XPAD];
    const float* xp = &xs[n*XPAD];
    for (int d = 0; d < DD; ++d) {
        float av = ap[d], xv = xp[d];
        const float2* wr = (const float2*)&WrelT[d*DN + cbase];
        const float2* wo = (const float2*)&WrootT[d*DN + cbase];
        #pragma unroll
        for (int j2 = 0; j2 < 25; ++j2) {
            float2 r2 = wr[j2], o2 = wo[j2];
            acc[2*j2]   += av*r2.x + xv*o2.x;
            acc[2*j2+1] += av*r2.y + xv*o2.y;
        }
    }
    #pragma unroll
    for (int j = 0; j < 50; ++j) {
        int c = cbase + j;
        float v = (acc[j] + brel[c]) * bnd_s[c] + bnd_t[c];
        hsh[n*HPAD + c] = fmaxf(v, 0.f);
    }
    __syncthreads();

    // TopK score
    if (tid < NPG) {
        float s = 0.f;
        const float* hp = &hsh[tid*HPAD];
        for (int c = 0; c < DN; ++c) s += hp[c]*tw[c];
        score[tid] = tanhf(s * rsqrtf(red[0]));
    }
    __syncthreads();
    // stable rank (matches jax top_k tie-breaking: lower index wins)
    if (tid < NPG) {
        float sn = score[tid];
        int r = 0;
        for (int m2 = 0; m2 < NPG; ++m2) {
            float sv = score[m2];
            r += (sv > sn) || (sv == sn && m2 < tid);
        }
        flag[tid] = (r < KTOP) ? 1 : 0;
    }
    __syncthreads();

    // readouts: mm0 (all nodes), mm1 (topk scaled); dx = relu(mm0 + 3*mm1)
    if (tid < DN) {
        const int c = tid;
        float mx = -1e30f, sum = 0.f, mxs = -1e30f, sums = 0.f;
        for (int n2 = 0; n2 < NPG; ++n2) {
            float v = hsh[n2*HPAD + c];
            mx = fmaxf(mx, v); sum += v;
            if (flag[n2]) {
                float w = v * score[n2];
                mxs = fmaxf(mxs, w); sums += w;
            }
        }
        g_dx[(size_t)g*400 + c]       = fmaxf(mx + 3.f*mxs, 0.f);
        g_dx[(size_t)g*400 + DN + c]  = fmaxf(sum*(1.f/NPG) + 3.f*(sums*(1.f/KTOP)), 0.f);
    }
}

// ============================================================================
// resp = [f1 | dx] @ Wp^T + bp
// ============================================================================
__global__ __launch_bounds__(256) void resp_kernel(
    const float* __restrict__ Wp, const float* __restrict__ bp,
    float* __restrict__ out)
{
    const int row = blockIdx.x * 8 + (threadIdx.x >> 5);
    const int lane = threadIdx.x & 31;
    float s = 0.f;
    for (int i = lane; i < 500; i += 32) {
        float z = (i < H2) ? out[(size_t)row*H2 + i] : g_dx[(size_t)row*400 + (i - H2)];
        s += z * Wp[i];
    }
    #pragma unroll
    for (int o = 16; o; o >>= 1) s += __shfl_down_sync(0xffffffffu, s, o);
    if (lane == 0) out[(size_t)2*NB*H2 + row] = s + bp[0];
}

// ============================================================================
extern "C" void kernel_launch(void* const* d_in, const int* in_sizes, int n_in,
                              void* d_out, int out_size)
{
    const float* x1     = (const float*)d_in[0];
    const float* x2     = (const float*)d_in[1];
    // d_in[2] batch_idx, d_in[3] edge_attr: unused
    const int*   eidx   = (const int*)d_in[4];
    const float* drug_x = (const float*)d_in[5];
    const float* bn0_s  = (const float*)d_in[6];
    const float* bn0_t  = (const float*)d_in[7];
    const float* W1     = (const float*)d_in[8];
    const float* b1     = (const float*)d_in[9];
    const float* bn1_s  = (const float*)d_in[10];
    const float* bn1_t  = (const float*)d_in[11];
    const float* W2     = (const float*)d_in[12];
    const float* b2     = (const float*)d_in[13];
    const float* bn2_s  = (const float*)d_in[14];
    const float* bn2_t  = (const float*)d_in[15];
    const float* Wrel   = (const float*)d_in[16];
    const float* brel   = (const float*)d_in[17];
    const float* Wroot  = (const float*)d_in[18];
    const float* bnd_s  = (const float*)d_in[19];
    const float* bnd_t  = (const float*)d_in[20];
    const float* topk_w = (const float*)d_in[21];
    const float* Wp     = (const float*)d_in[22];
    const float* bp     = (const float*)d_in[23];
    float* out = (float*)d_out;

    cudaFuncSetAttribute(drug_kernel, cudaFuncAttributeMaxDynamicSharedMemorySize,
                         SM_DRUG_BYTES);

    dim3 g1(H1 / G1_BN, M_TOT / G1_BM);   // (16, 32)
    gemm1_kernel<<<g1, 256>>>(x1, x2, W1, b1, bn0_s, bn0_t, bn1_s, bn1_t);
    gemm2_kernel<<<M_TOT / 32, 256>>>(W2, b2, bn2_s, bn2_t, out);
    drug_kernel<<<NG, 256, SM_DRUG_BYTES>>>(drug_x, eidx, Wrel, brel, Wroot,
                                            bnd_s, bnd_t, topk_w);
    resp_kernel<<<NG / 8, 256>>>(Wp, bp, out);
}

// round 4
// speedup vs baseline: 1.6386x; 1.6386x over previous
#include <cuda_runtime.h>
#include <cuda_bf16.h>
#include <math.h>
#include <stdint.h>

#define NB      2048
#define EXPR    8000
#define H1      1024
#define H2      100
#define M_TOT   4096
#define DD      78
#define DN      200
#define NPG     64
#define EPG     128
#define NG      2048
#define ET_TOT  262144
#define KTOP    52

__device__ float g_h1[M_TOT * H1];
__device__ float g_dx[NG * 400];
__device__ __nv_bfloat16 g_Ahi[(size_t)M_TOT * EXPR];
__device__ __nv_bfloat16 g_Alo[(size_t)M_TOT * EXPR];
__device__ __nv_bfloat16 g_Bhi[(size_t)H1 * EXPR];
__device__ __nv_bfloat16 g_Blo[(size_t)H1 * EXPR];

// ---------------- helpers ----------------
__device__ __forceinline__ unsigned smem_u32(const void* p) {
    unsigned a;
    asm("{ .reg .u64 t; cvta.to.shared.u64 t, %1; cvt.u32.u64 %0, t; }" : "=r"(a) : "l"(p));
    return a;
}
__device__ __forceinline__ void cpa16(unsigned s, const void* g) {
    asm volatile("cp.async.cg.shared.global [%0], [%1], 16;" :: "r"(s), "l"(g));
}
__device__ __forceinline__ void cpa_commit() { asm volatile("cp.async.commit_group;" ::: "memory"); }
template<int N> __device__ __forceinline__ void cpa_wait() {
    asm volatile("cp.async.wait_group %0;" :: "n"(N) : "memory");
}
__device__ __forceinline__ void ldmx4(unsigned* r, unsigned addr) {
    asm volatile("ldmatrix.sync.aligned.m8n8.x4.shared.b16 {%0,%1,%2,%3}, [%4];"
        : "=r"(r[0]), "=r"(r[1]), "=r"(r[2]), "=r"(r[3]) : "r"(addr));
}
__device__ __forceinline__ void mma16816(float* d, const unsigned* a, const unsigned* b) {
    asm volatile("mma.sync.aligned.m16n8k16.row.col.f32.bf16.bf16.f32 "
        "{%0,%1,%2,%3}, {%4,%5,%6,%7}, {%8,%9}, {%0,%1,%2,%3};"
        : "+f"(d[0]), "+f"(d[1]), "+f"(d[2]), "+f"(d[3])
        : "r"(a[0]), "r"(a[1]), "r"(a[2]), "r"(a[3]), "r"(b[0]), "r"(b[1]));
}

// ---------------- prep: bf16 hi/lo split ----------------
__device__ __forceinline__ void split4(__nv_bfloat16* hi, __nv_bfloat16* lo, float4 v) {
    __nv_bfloat16 h0=__float2bfloat16_rn(v.x), h1=__float2bfloat16_rn(v.y);
    __nv_bfloat16 h2=__float2bfloat16_rn(v.z), h3=__float2bfloat16_rn(v.w);
    union { __nv_bfloat16 b[4]; uint2 u; } H, L;
    H.b[0]=h0; H.b[1]=h1; H.b[2]=h2; H.b[3]=h3;
    L.b[0]=__float2bfloat16_rn(v.x-__bfloat162float(h0));
    L.b[1]=__float2bfloat16_rn(v.y-__bfloat162float(h1));
    L.b[2]=__float2bfloat16_rn(v.z-__bfloat162float(h2));
    L.b[3]=__float2bfloat16_rn(v.w-__bfloat162float(h3));
    *(uint2*)hi = H.u;  *(uint2*)lo = L.u;
}

__global__ __launch_bounds__(256) void prep_kernel(
    const float* __restrict__ x1, const float* __restrict__ x2,
    const float* __restrict__ W1,
    const float* __restrict__ bn0_s, const float* __restrict__ bn0_t)
{
    const long NA = (long)M_TOT * 2000;
    const long NT4 = NA + (long)H1 * 2000;
    long i = (long)blockIdx.x * 256 + threadIdx.x;
    if (i >= NT4) return;
    if (i < NA) {
        int row = (int)(i / 2000), k4 = (int)(i % 2000);
        const float* src = (row < NB) ? (x1 + (size_t)row * EXPR) : (x2 + (size_t)(row - NB) * EXPR);
        float4 v = *(const float4*)(src + k4 * 4);
        float4 s = *(const float4*)(bn0_s + k4 * 4);
        float4 t = *(const float4*)(bn0_t + k4 * 4);
        v.x = v.x*s.x + t.x;  v.y = v.y*s.y + t.y;  v.z = v.z*s.z + t.z;  v.w = v.w*s.w + t.w;
        size_t eo = (size_t)row * EXPR + (size_t)k4 * 4;
        split4(g_Ahi + eo, g_Alo + eo, v);
    } else {
        long j = i - NA;
        int row = (int)(j / 2000), k4 = (int)(j % 2000);
        float4 v = *(const float4*)(W1 + (size_t)row * EXPR + k4 * 4);
        size_t eo = (size_t)row * EXPR + (size_t)k4 * 4;
        split4(g_Bhi + eo, g_Blo + eo, v);
    }
}

// ---------------- GEMM1 via mma.sync (bf16 3-way split) ----------------
// CTA tile 256(m) x 128(n), k-chunk 32, 3-stage cp.async, 512 threads.
#define KC    32
#define NCH   250
#define AST   40                      // padded row stride (bf16 elems), 80B
#define OFF_AH 0
#define OFF_AL 20480                  // 256*40*2
#define OFF_BH 40960
#define OFF_BL 51200                  // + 128*40*2
#define STG    61440
#define G1_DSMEM (3 * STG)

__global__ void __launch_bounds__(512, 1) gemm1_mma(
    const float* __restrict__ b1, const float* __restrict__ bn1_s,
    const float* __restrict__ bn1_t)
{
    extern __shared__ char dynsm[];
    __shared__ float s_alpha[128], s_beta[128];
    const unsigned sb = smem_u32(dynsm);
    const int tid = threadIdx.x;
    const int warp = tid >> 5, lane = tid & 31;
    const int m0 = blockIdx.y * 256;
    const int n0 = blockIdx.x * 128;
    const int wm = (warp >> 2) * 64;      // warp m offset (4 warps in m)
    const int wn = (warp & 3) * 32;       // warp n offset (4 warps in n)

    if (tid < 128) {
        float al = bn1_s[n0 + tid];
        s_alpha[tid] = al;
        s_beta[tid]  = b1[n0 + tid] * al + bn1_t[n0 + tid];
    }

    auto load_chunk = [&](int c, int s) {
        const unsigned st = sb + s * STG;
        const long k0 = (long)c * KC;
        #pragma unroll
        for (int t = 0; t < 2; ++t) {                // A: 1024 chunks
            int i = tid + (t << 9);
            int r = i >> 2, q = i & 3;
            unsigned off = r * 80 + q * 16;
            size_t go = (size_t)(m0 + r) * EXPR + k0 + q * 8;
            cpa16(st + OFF_AH + off, g_Ahi + go);
            cpa16(st + OFF_AL + off, g_Alo + go);
        }
        {                                            // B: 512 chunks
            int r = tid >> 2, q = tid & 3;
            unsigned off = r * 80 + q * 16;
            size_t go = (size_t)(n0 + r) * EXPR + k0 + q * 8;
            cpa16(st + OFF_BH + off, g_Bhi + go);
            cpa16(st + OFF_BL + off, g_Blo + go);
        }
        cpa_commit();
    };

    float acc[4][4][4];
    #pragma unroll
    for (int i = 0; i < 4; ++i)
        #pragma unroll
        for (int j = 0; j < 4; ++j)
            #pragma unroll
            for (int q = 0; q < 4; ++q) acc[i][j][q] = 0.f;

    load_chunk(0, 0);
    load_chunk(1, 1);
    load_chunk(2, 2);

    const int arow = lane & 15;
    const int acol = (lane >> 4) << 3;

    for (int c = 0; c < NCH; ++c) {
        const int s = c - (c / 3) * 3;
        const unsigned aH = sb + s * STG;
        const unsigned aL = aH + OFF_AL;
        const unsigned bH = aH + OFF_BH;
        const unsigned bL = aH + OFF_BL;
        cpa_wait<2>();
        __syncthreads();

        #pragma unroll
        for (int ks = 0; ks < KC; ks += 16) {
            unsigned ah[16], bh[8], u[16];
            #pragma unroll
            for (int i = 0; i < 4; ++i)
                ldmx4(&ah[4*i], aH + ((wm + i*16 + arow) * AST + ks + acol) * 2);
            #pragma unroll
            for (int j2 = 0; j2 < 2; ++j2) {
                unsigned tr[4];
                ldmx4(tr, bH + ((wn + j2*16 + arow) * AST + ks + acol) * 2);
                bh[4*j2 + 0] = tr[0];  bh[4*j2 + 1] = tr[2];
                bh[4*j2 + 2] = tr[1];  bh[4*j2 + 3] = tr[3];
            }
            #pragma unroll
            for (int i = 0; i < 4; ++i)
                #pragma unroll
                for (int j = 0; j < 4; ++j)
                    mma16816(acc[i][j], &ah[4*i], &bh[2*j]);
            // B-lo
            #pragma unroll
            for (int j2 = 0; j2 < 2; ++j2) {
                unsigned tr[4];
                ldmx4(tr, bL + ((wn + j2*16 + arow) * AST + ks + acol) * 2);
                u[4*j2 + 0] = tr[0];  u[4*j2 + 1] = tr[2];
                u[4*j2 + 2] = tr[1];  u[4*j2 + 3] = tr[3];
            }
            #pragma unroll
            for (int i = 0; i < 4; ++i)
                #pragma unroll
                for (int j = 0; j < 4; ++j)
                    mma16816(acc[i][j], &ah[4*i], &u[2*j]);
            // A-lo
            #pragma unroll
            for (int i = 0; i < 4; ++i)
                ldmx4(&u[4*i], aL + ((wm + i*16 + arow) * AST + ks + acol) * 2);
            #pragma unroll
            for (int i = 0; i < 4; ++i)
                #pragma unroll
                for (int j = 0; j < 4; ++j)
                    mma16816(acc[i][j], &u[4*i], &bh[2*j]);
        }
        __syncthreads();
        if (c + 3 < NCH) load_chunk(c + 3, s);
    }

    // epilogue: relu(acc*alpha + beta) -> g_h1
    const int er = lane >> 2, ec = (lane & 3) * 2;
    #pragma unroll
    for (int i = 0; i < 4; ++i) {
        #pragma unroll
        for (int j = 0; j < 4; ++j) {
            int nl = wn + j*8 + ec;
            float a0 = s_alpha[nl], a1 = s_alpha[nl+1];
            float e0 = s_beta[nl],  e1 = s_beta[nl+1];
            int mg0 = m0 + wm + i*16 + er;
            float2 v0, v1;
            v0.x = fmaxf(acc[i][j][0]*a0 + e0, 0.f);
            v0.y = fmaxf(acc[i][j][1]*a1 + e1, 0.f);
            v1.x = fmaxf(acc[i][j][2]*a0 + e0, 0.f);
            v1.y = fmaxf(acc[i][j][3]*a1 + e1, 0.f);
            *(float2*)&g_h1[(size_t)mg0 * H1 + n0 + nl]       = v0;
            *(float2*)&g_h1[(size_t)(mg0 + 8) * H1 + n0 + nl] = v1;
        }
    }
}

// ---------------- GEMM2 ----------------
#define G2_BK 16
__global__ __launch_bounds__(256) void gemm2_kernel(
    const float* __restrict__ W2, const float* __restrict__ b2,
    const float* __restrict__ bn2_s, const float* __restrict__ bn2_t,
    float* __restrict__ out)
{
    __shared__ float As[32 * G2_BK];
    __shared__ float Bs[112 * 17];
    const int tid = threadIdx.x;
    const int tx = tid & 15, ty = tid >> 4;
    const int m0 = blockIdx.x * 32;
    const int rowA = tid >> 3, c2 = (tid & 7) * 2;
    const float* pA = g_h1 + (size_t)(m0 + rowA) * H1 + c2;

    float2 aPre;  float bPre[7];
    aPre = *(const float2*)(pA);
    #pragma unroll
    for (int it = 0; it < 7; ++it) {
        int i = tid + it*256;
        if (i < 1600) bPre[it] = W2[(size_t)(i/16) * H1 + (i & 15)];
    }
    As[rowA*G2_BK + c2] = aPre.x;  As[rowA*G2_BK + c2 + 1] = aPre.y;
    #pragma unroll
    for (int it = 0; it < 7; ++it) {
        int i = tid + it*256;
        if (i < 1600) Bs[(i/16)*17 + (i & 15)] = bPre[it];
    }
    __syncthreads();

    float acc0[7], acc1[7];
    #pragma unroll
    for (int j = 0; j < 7; ++j) { acc0[j] = 0.f; acc1[j] = 0.f; }

    const int NT_K = H1 / G2_BK;
    for (int kt = 0; kt < NT_K; ++kt) {
        const bool has = (kt + 1) < NT_K;
        const int k0n = (kt + 1) * G2_BK;
        if (has) {
            aPre = *(const float2*)(pA + k0n);
            #pragma unroll
            for (int it = 0; it < 7; ++it) {
                int i = tid + it*256;
                if (i < 1600) bPre[it] = W2[(size_t)(i/16) * H1 + k0n + (i & 15)];
            }
        }
        #pragma unroll
        for (int kk = 0; kk < G2_BK; ++kk) {
            float a0 = As[ty*G2_BK + kk];
            float a1 = As[(ty + 16)*G2_BK + kk];
            #pragma unroll
            for (int j = 0; j < 7; ++j) {
                float bv = Bs[(tx + 16*j)*17 + kk];
                acc0[j] += a0 * bv;
                acc1[j] += a1 * bv;
            }
        }
        __syncthreads();
        if (has) {
            As[rowA*G2_BK + c2] = aPre.x;  As[rowA*G2_BK + c2 + 1] = aPre.y;
            #pragma unroll
            for (int it = 0; it < 7; ++it) {
                int i = tid + it*256;
                if (i < 1600) Bs[(i/16)*17 + (i & 15)] = bPre[it];
            }
            __syncthreads();
        }
    }

    #pragma unroll
    for (int j = 0; j < 7; ++j) {
        int n = tx + 16*j;
        if (n >= H2) continue;
        float al = bn2_s[n];
        float be = b2[n]*al + bn2_t[n];
        int m_a = m0 + ty, m_b = m0 + ty + 16;
        float va = fmaxf(acc0[j]*al + be, 0.f);
        float vb = fmaxf(acc1[j]*al + be, 0.f);
        size_t oa = (m_a < NB) ? ((size_t)m_a*H2 + n) : ((size_t)NB*H2 + (size_t)(m_a - NB)*H2 + n);
        size_t ob = (m_b < NB) ? ((size_t)m_b*H2 + n) : ((size_t)NB*H2 + (size_t)(m_b - NB)*H2 + n);
        out[oa] = va;
        out[ob] = vb;
    }
}

// ---------------- Drug encoder ----------------
#define XPAD 79
#define HPAD 201
#define SM_WREL   0
#define SM_WROOT  (SM_WREL  + DD*DN)
#define SM_XS     (SM_WROOT + DD*DN)
#define SM_AGG    (SM_XS    + NPG*XPAD)
#define SM_H      (SM_AGG   + NPG*XPAD)
#define SM_TW     (SM_H     + NPG*HPAD)
#define SM_SCORE  (SM_TW    + DN)
#define SM_RED    (SM_SCORE + NPG)
#define SM_FLOATS (SM_RED   + 1)
#define SM_DRUG_BYTES (SM_FLOATS*4 + (NPG + 2*EPG)*4)

__global__ __launch_bounds__(256) void drug_kernel(
    const float* __restrict__ drug_x, const int* __restrict__ edge_index,
    const float* __restrict__ Wrel, const float* __restrict__ brel,
    const float* __restrict__ Wroot,
    const float* __restrict__ bnd_s, const float* __restrict__ bnd_t,
    const float* __restrict__ topk_w)
{
    extern __shared__ float sm[];
    float* WrelT  = sm + SM_WREL;
    float* WrootT = sm + SM_WROOT;
    float* xs     = sm + SM_XS;
    float* agg    = sm + SM_AGG;
    float* hsh    = sm + SM_H;
    float* tw     = sm + SM_TW;
    float* score  = sm + SM_SCORE;
    float* red    = sm + SM_RED;
    int* flag = (int*)(sm + SM_FLOATS);
    int* es   = flag + NPG;
    int* ed   = es + EPG;

    const int g = blockIdx.x;
    const int tid = threadIdx.x;

    for (int i = tid; i < DN*DD; i += 256) {
        int c = i / DD, d = i % DD;
        WrelT[d*DN + c]  = Wrel[i];
        WrootT[d*DN + c] = Wroot[i];
    }
    for (int i = tid; i < NPG*DD; i += 256) {
        int n = i / DD, d = i % DD;
        xs[n*XPAD + d]  = drug_x[(size_t)(g*NPG + n)*DD + d];
        agg[n*XPAD + d] = 0.f;
    }
    if (tid < DN) tw[tid] = topk_w[tid];
    if (tid < EPG) {
        es[tid] = edge_index[g*EPG + tid] - g*NPG;
        ed[tid] = edge_index[ET_TOT + g*EPG + tid] - g*NPG;
    }
    if (tid == 0) red[0] = 0.f;
    __syncthreads();

    if (tid < DN) atomicAdd(&red[0], tw[tid]*tw[tid]);
    if (tid < DD) {
        const int d = tid;
        for (int e = 0; e < EPG; ++e)
            agg[ed[e]*XPAD + d] += xs[es[e]*XPAD + d];
    }
    __syncthreads();

    const int n = tid & 63;
    const int cbase = (tid >> 6) * 50;
    float acc[50];
    #pragma unroll
    for (int j = 0; j < 50; ++j) acc[j] = 0.f;

    const float* ap = &agg[n*XPAD];
    const float* xp = &xs[n*XPAD];
    for (int d = 0; d < DD; ++d) {
        float av = ap[d], xv = xp[d];
        const float2* wr = (const float2*)&WrelT[d*DN + cbase];
        const float2* wo = (const float2*)&WrootT[d*DN + cbase];
        #pragma unroll
        for (int j2 = 0; j2 < 25; ++j2) {
            float2 r2 = wr[j2], o2 = wo[j2];
            acc[2*j2]   += av*r2.x + xv*o2.x;
            acc[2*j2+1] += av*r2.y + xv*o2.y;
        }
    }
    #pragma unroll
    for (int j = 0; j < 50; ++j) {
        int c = cbase + j;
        float v = (acc[j] + brel[c]) * bnd_s[c] + bnd_t[c];
        hsh[n*HPAD + c] = fmaxf(v, 0.f);
    }
    __syncthreads();

    if (tid < NPG) {
        float s = 0.f;
        const float* hp = &hsh[tid*HPAD];
        for (int c = 0; c < DN; ++c) s += hp[c]*tw[c];
        score[tid] = tanhf(s * rsqrtf(red[0]));
    }
    __syncthreads();
    if (tid < NPG) {
        float sn = score[tid];
        int r = 0;
        for (int m2 = 0; m2 < NPG; ++m2) {
            float sv = score[m2];
            r += (sv > sn) || (sv == sn && m2 < tid);
        }
        flag[tid] = (r < KTOP) ? 1 : 0;
    }
    __syncthreads();

    if (tid < DN) {
        const int c = tid;
        float mx = -1e30f, sum = 0.f, mxs = -1e30f, sums = 0.f;
        for (int n2 = 0; n2 < NPG; ++n2) {
            float v = hsh[n2*HPAD + c];
            mx = fmaxf(mx, v); sum += v;
            if (flag[n2]) {
                float w = v * score[n2];
                mxs = fmaxf(mxs, w); sums += w;
            }
        }
        g_dx[(size_t)g*400 + c]       = fmaxf(mx + 3.f*mxs, 0.f);
        g_dx[(size_t)g*400 + DN + c]  = fmaxf(sum*(1.f/NPG) + 3.f*(sums*(1.f/KTOP)), 0.f);
    }
}

// ---------------- resp ----------------
__global__ __launch_bounds__(256) void resp_kernel(
    const float* __restrict__ Wp, const float* __restrict__ bp,
    float* __restrict__ out)
{
    const int row = blockIdx.x * 8 + (threadIdx.x >> 5);
    const int lane = threadIdx.x & 31;
    float s = 0.f;
    for (int i = lane; i < 500; i += 32) {
        float z = (i < H2) ? out[(size_t)row*H2 + i] : g_dx[(size_t)row*400 + (i - H2)];
        s += z * Wp[i];
    }
    #pragma unroll
    for (int o = 16; o; o >>= 1) s += __shfl_down_sync(0xffffffffu, s, o);
    if (lane == 0) out[(size_t)2*NB*H2 + row] = s + bp[0];
}

// ============================================================================
extern "C" void kernel_launch(void* const* d_in, const int* in_sizes, int n_in,
                              void* d_out, int out_size)
{
    const float* x1     = (const float*)d_in[0];
    const float* x2     = (const float*)d_in[1];
    const int*   eidx   = (const int*)d_in[4];
    const float* drug_x = (const float*)d_in[5];
    const float* bn0_s  = (const float*)d_in[6];
    const float* bn0_t  = (const float*)d_in[7];
    const float* W1     = (const float*)d_in[8];
    const float* b1     = (const float*)d_in[9];
    const float* bn1_s  = (const float*)d_in[10];
    const float* bn1_t  = (const float*)d_in[11];
    const float* W2     = (const float*)d_in[12];
    const float* b2     = (const float*)d_in[13];
    const float* bn2_s  = (const float*)d_in[14];
    const float* bn2_t  = (const float*)d_in[15];
    const float* Wrel   = (const float*)d_in[16];
    const float* brel   = (const float*)d_in[17];
    const float* Wroot  = (const float*)d_in[18];
    const float* bnd_s  = (const float*)d_in[19];
    const float* bnd_t  = (const float*)d_in[20];
    const float* topk_w = (const float*)d_in[21];
    const float* Wp     = (const float*)d_in[22];
    const float* bp     = (const float*)d_in[23];
    float* out = (float*)d_out;

    cudaFuncSetAttribute(drug_kernel, cudaFuncAttributeMaxDynamicSharedMemorySize, SM_DRUG_BYTES);
    cudaFuncSetAttribute(gemm1_mma, cudaFuncAttributeMaxDynamicSharedMemorySize, G1_DSMEM);

    const long NT4 = (long)M_TOT * 2000 + (long)H1 * 2000;
    prep_kernel<<<(int)((NT4 + 255) / 256), 256>>>(x1, x2, W1, bn0_s, bn0_t);
    gemm1_mma<<<dim3(8, 16), 512, G1_DSMEM>>>(b1, bn1_s, bn1_t);
    gemm2_kernel<<<M_TOT / 32, 256>>>(W2, b2, bn2_s, bn2_t, out);
    drug_kernel<<<NG, 256, SM_DRUG_BYTES>>>(drug_x, eidx, Wrel, brel, Wroot, bnd_s, bnd_t, topk_w);
    resp_kernel<<<NG / 8, 256>>>(Wp, bp, out);
}

// round 5
// speedup vs baseline: 1.9740x; 1.2047x over previous
#include <cuda_runtime.h>
#include <cuda_bf16.h>
#include <math.h>
#include <stdint.h>

#define NB      2048
#define EXPR    8000
#define H1      1024
#define H2      100
#define M_TOT   4096
#define DD      78
#define DN      200
#define NPG     64
#define EPG     128
#define NG      2048
#define ET_TOT  262144
#define KTOP    52

__device__ float g_h1[M_TOT * H1];
__device__ float g_dx[NG * 400];
__device__ __nv_bfloat16 g_Ahi[(size_t)M_TOT * EXPR];
__device__ __nv_bfloat16 g_Alo[(size_t)M_TOT * EXPR];
__device__ __nv_bfloat16 g_Bhi[(size_t)H1 * EXPR];
__device__ __nv_bfloat16 g_Blo[(size_t)H1 * EXPR];
__device__ float4 g_Wp[DD * 100];      // [d][c/2] = {wrel_c, wrel_c+1, wroot_c, wroot_c+1}
__device__ float g_wa[DN], g_wb[DN];   // folded bnd scale/shift
__device__ float g_winv;               // 1/||topk_w||

// ---------------- helpers ----------------
__device__ __forceinline__ unsigned smem_u32(const void* p) {
    unsigned a;
    asm("{ .reg .u64 t; cvta.to.shared.u64 t, %1; cvt.u32.u64 %0, t; }" : "=r"(a) : "l"(p));
    return a;
}
__device__ __forceinline__ void cpa16(unsigned s, const void* g) {
    asm volatile("cp.async.cg.shared.global [%0], [%1], 16;" :: "r"(s), "l"(g));
}
__device__ __forceinline__ void cpa_commit() { asm volatile("cp.async.commit_group;" ::: "memory"); }
template<int N> __device__ __forceinline__ void cpa_wait() {
    asm volatile("cp.async.wait_group %0;" :: "n"(N) : "memory");
}
__device__ __forceinline__ void ldmx4(unsigned* r, unsigned addr) {
    asm volatile("ldmatrix.sync.aligned.m8n8.x4.shared.b16 {%0,%1,%2,%3}, [%4];"
        : "=r"(r[0]), "=r"(r[1]), "=r"(r[2]), "=r"(r[3]) : "r"(addr));
}
__device__ __forceinline__ void mma16816(float* d, const unsigned* a, const unsigned* b) {
    asm volatile("mma.sync.aligned.m16n8k16.row.col.f32.bf16.bf16.f32 "
        "{%0,%1,%2,%3}, {%4,%5,%6,%7}, {%8,%9}, {%0,%1,%2,%3};"
        : "+f"(d[0]), "+f"(d[1]), "+f"(d[2]), "+f"(d[3])
        : "r"(a[0]), "r"(a[1]), "r"(a[2]), "r"(a[3]), "r"(b[0]), "r"(b[1]));
}

// ---------------- prep: bf16 hi/lo split ----------------
__device__ __forceinline__ void split4(__nv_bfloat16* hi, __nv_bfloat16* lo, float4 v) {
    __nv_bfloat16 h0=__float2bfloat16_rn(v.x), h1=__float2bfloat16_rn(v.y);
    __nv_bfloat16 h2=__float2bfloat16_rn(v.z), h3=__float2bfloat16_rn(v.w);
    union { __nv_bfloat16 b[4]; uint2 u; } H, L;
    H.b[0]=h0; H.b[1]=h1; H.b[2]=h2; H.b[3]=h3;
    L.b[0]=__float2bfloat16_rn(v.x-__bfloat162float(h0));
    L.b[1]=__float2bfloat16_rn(v.y-__bfloat162float(h1));
    L.b[2]=__float2bfloat16_rn(v.z-__bfloat162float(h2));
    L.b[3]=__float2bfloat16_rn(v.w-__bfloat162float(h3));
    *(uint2*)hi = H.u;  *(uint2*)lo = L.u;
}

__global__ __launch_bounds__(256) void prep_kernel(
    const float* __restrict__ x1, const float* __restrict__ x2,
    const float* __restrict__ W1,
    const float* __restrict__ bn0_s, const float* __restrict__ bn0_t)
{
    const long NA = (long)M_TOT * 2000;
    const long NT4 = NA + (long)H1 * 2000;
    long i = (long)blockIdx.x * 256 + threadIdx.x;
    if (i >= NT4) return;
    if (i < NA) {
        int row = (int)(i / 2000), k4 = (int)(i % 2000);
        const float* src = (row < NB) ? (x1 + (size_t)row * EXPR) : (x2 + (size_t)(row - NB) * EXPR);
        float4 v = *(const float4*)(src + k4 * 4);
        float4 s = *(const float4*)(bn0_s + k4 * 4);
        float4 t = *(const float4*)(bn0_t + k4 * 4);
        v.x = v.x*s.x + t.x;  v.y = v.y*s.y + t.y;  v.z = v.z*s.z + t.z;  v.w = v.w*s.w + t.w;
        size_t eo = (size_t)row * EXPR + (size_t)k4 * 4;
        split4(g_Ahi + eo, g_Alo + eo, v);
    } else {
        long j = i - NA;
        int row = (int)(j / 2000), k4 = (int)(j % 2000);
        float4 v = *(const float4*)(W1 + (size_t)row * EXPR + k4 * 4);
        size_t eo = (size_t)row * EXPR + (size_t)k4 * 4;
        split4(g_Bhi + eo, g_Blo + eo, v);
    }
}

// ---------------- weight prep for drug encoder ----------------
__global__ __launch_bounds__(256) void wprep_kernel(
    const float* __restrict__ Wrel, const float* __restrict__ Wroot,
    const float* __restrict__ brel,
    const float* __restrict__ bnd_s, const float* __restrict__ bnd_t,
    const float* __restrict__ topk_w)
{
    int i = blockIdx.x * 256 + threadIdx.x;
    if (i < DD * 100) {
        int d = i / 100, cp = i % 100;
        int c0 = cp * 2;
        g_Wp[i] = make_float4(Wrel[c0*DD + d], Wrel[(c0+1)*DD + d],
                              Wroot[c0*DD + d], Wroot[(c0+1)*DD + d]);
    }
    if (i < DN) {
        float al = bnd_s[i];
        g_wa[i] = al;
        g_wb[i] = brel[i]*al + bnd_t[i];
    }
    if (i == 0) {
        float s = 0.f;
        for (int c = 0; c < DN; ++c) s += topk_w[c]*topk_w[c];
        g_winv = rsqrtf(s);
    }
}

// ---------------- GEMM1 via mma.sync (bf16 3-way split) ----------------
#define KC    32
#define NCH   250
#define AST   40
#define OFF_AH 0
#define OFF_AL 20480
#define OFF_BH 40960
#define OFF_BL 51200
#define STG    61440
#define G1_DSMEM (3 * STG)

__global__ void __launch_bounds__(512, 1) gemm1_mma(
    const float* __restrict__ b1, const float* __restrict__ bn1_s,
    const float* __restrict__ bn1_t)
{
    extern __shared__ char dynsm[];
    __shared__ float s_alpha[128], s_beta[128];
    const unsigned sb = smem_u32(dynsm);
    const int tid = threadIdx.x;
    const int warp = tid >> 5, lane = tid & 31;
    const int m0 = blockIdx.y * 256;
    const int n0 = blockIdx.x * 128;
    const int wm = (warp >> 2) * 64;
    const int wn = (warp & 3) * 32;

    if (tid < 128) {
        float al = bn1_s[n0 + tid];
        s_alpha[tid] = al;
        s_beta[tid]  = b1[n0 + tid] * al + bn1_t[n0 + tid];
    }

    auto load_chunk = [&](int c, int s) {
        const unsigned st = sb + s * STG;
        const long k0 = (long)c * KC;
        #pragma unroll
        for (int t = 0; t < 2; ++t) {
            int i = tid + (t << 9);
            int r = i >> 2, q = i & 3;
            unsigned off = r * 80 + q * 16;
            size_t go = (size_t)(m0 + r) * EXPR + k0 + q * 8;
            cpa16(st + OFF_AH + off, g_Ahi + go);
            cpa16(st + OFF_AL + off, g_Alo + go);
        }
        {
            int r = tid >> 2, q = tid & 3;
            unsigned off = r * 80 + q * 16;
            size_t go = (size_t)(n0 + r) * EXPR + k0 + q * 8;
            cpa16(st + OFF_BH + off, g_Bhi + go);
            cpa16(st + OFF_BL + off, g_Blo + go);
        }
        cpa_commit();
    };

    float acc[4][4][4];
    #pragma unroll
    for (int i = 0; i < 4; ++i)
        #pragma unroll
        for (int j = 0; j < 4; ++j)
            #pragma unroll
            for (int q = 0; q < 4; ++q) acc[i][j][q] = 0.f;

    load_chunk(0, 0);
    load_chunk(1, 1);
    load_chunk(2, 2);

    const int arow = lane & 15;
    const int acol = (lane >> 4) << 3;

    for (int c = 0; c < NCH; ++c) {
        const int s = c - (c / 3) * 3;
        const unsigned aH = sb + s * STG;
        const unsigned aL = aH + OFF_AL;
        const unsigned bH = aH + OFF_BH;
        const unsigned bL = aH + OFF_BL;
        cpa_wait<2>();
        __syncthreads();

        #pragma unroll
        for (int ks = 0; ks < KC; ks += 16) {
            unsigned ah[16], bh[8], u[16];
            #pragma unroll
            for (int i = 0; i < 4; ++i)
                ldmx4(&ah[4*i], aH + ((wm + i*16 + arow) * AST + ks + acol) * 2);
            #pragma unroll
            for (int j2 = 0; j2 < 2; ++j2) {
                unsigned tr[4];
                ldmx4(tr, bH + ((wn + j2*16 + arow) * AST + ks + acol) * 2);
                bh[4*j2 + 0] = tr[0];  bh[4*j2 + 1] = tr[2];
                bh[4*j2 + 2] = tr[1];  bh[4*j2 + 3] = tr[3];
            }
            #pragma unroll
            for (int i = 0; i < 4; ++i)
                #pragma unroll
                for (int j = 0; j < 4; ++j)
                    mma16816(acc[i][j], &ah[4*i], &bh[2*j]);
            #pragma unroll
            for (int j2 = 0; j2 < 2; ++j2) {
                unsigned tr[4];
                ldmx4(tr, bL + ((wn + j2*16 + arow) * AST + ks + acol) * 2);
                u[4*j2 + 0] = tr[0];  u[4*j2 + 1] = tr[2];
                u[4*j2 + 2] = tr[1];  u[4*j2 + 3] = tr[3];
            }
            #pragma unroll
            for (int i = 0; i < 4; ++i)
                #pragma unroll
                for (int j = 0; j < 4; ++j)
                    mma16816(acc[i][j], &ah[4*i], &u[2*j]);
            #pragma unroll
            for (int i = 0; i < 4; ++i)
                ldmx4(&u[4*i], aL + ((wm + i*16 + arow) * AST + ks + acol) * 2);
            #pragma unroll
            for (int i = 0; i < 4; ++i)
                #pragma unroll
                for (int j = 0; j < 4; ++j)
                    mma16816(acc[i][j], &u[4*i], &bh[2*j]);
        }
        __syncthreads();
        if (c + 3 < NCH) load_chunk(c + 3, s);
    }

    const int er = lane >> 2, ec = (lane & 3) * 2;
    #pragma unroll
    for (int i = 0; i < 4; ++i) {
        #pragma unroll
        for (int j = 0; j < 4; ++j) {
            int nl = wn + j*8 + ec;
            float a0 = s_alpha[nl], a1 = s_alpha[nl+1];
            float e0 = s_beta[nl],  e1 = s_beta[nl+1];
            int mg0 = m0 + wm + i*16 + er;
            float2 v0, v1;
            v0.x = fmaxf(acc[i][j][0]*a0 + e0, 0.f);
            v0.y = fmaxf(acc[i][j][1]*a1 + e1, 0.f);
            v1.x = fmaxf(acc[i][j][2]*a0 + e0, 0.f);
            v1.y = fmaxf(acc[i][j][3]*a1 + e1, 0.f);
            *(float2*)&g_h1[(size_t)mg0 * H1 + n0 + nl]       = v0;
            *(float2*)&g_h1[(size_t)(mg0 + 8) * H1 + n0 + nl] = v1;
        }
    }
}

// ---------------- GEMM2 ----------------
#define G2_BK 16
__global__ __launch_bounds__(256) void gemm2_kernel(
    const float* __restrict__ W2, const float* __restrict__ b2,
    const float* __restrict__ bn2_s, const float* __restrict__ bn2_t,
    float* __restrict__ out)
{
    __shared__ float As[32 * G2_BK];
    __shared__ float Bs[112 * 17];
    const int tid = threadIdx.x;
    const int tx = tid & 15, ty = tid >> 4;
    const int m0 = blockIdx.x * 32;
    const int rowA = tid >> 3, c2 = (tid & 7) * 2;
    const float* pA = g_h1 + (size_t)(m0 + rowA) * H1 + c2;

    float2 aPre;  float bPre[7];
    aPre = *(const float2*)(pA);
    #pragma unroll
    for (int it = 0; it < 7; ++it) {
        int i = tid + it*256;
        if (i < 1600) bPre[it] = W2[(size_t)(i/16) * H1 + (i & 15)];
    }
    As[rowA*G2_BK + c2] = aPre.x;  As[rowA*G2_BK + c2 + 1] = aPre.y;
    #pragma unroll
    for (int it = 0; it < 7; ++it) {
        int i = tid + it*256;
        if (i < 1600) Bs[(i/16)*17 + (i & 15)] = bPre[it];
    }
    __syncthreads();

    float acc0[7], acc1[7];
    #pragma unroll
    for (int j = 0; j < 7; ++j) { acc0[j] = 0.f; acc1[j] = 0.f; }

    const int NT_K = H1 / G2_BK;
    for (int kt = 0; kt < NT_K; ++kt) {
        const bool has = (kt + 1) < NT_K;
        const int k0n = (kt + 1) * G2_BK;
        if (has) {
            aPre = *(const float2*)(pA + k0n);
            #pragma unroll
            for (int it = 0; it < 7; ++it) {
                int i = tid + it*256;
                if (i < 1600) bPre[it] = W2[(size_t)(i/16) * H1 + k0n + (i & 15)];
            }
        }
        #pragma unroll
        for (int kk = 0; kk < G2_BK; ++kk) {
            float a0 = As[ty*G2_BK + kk];
            float a1 = As[(ty + 16)*G2_BK + kk];
            #pragma unroll
            for (int j = 0; j < 7; ++j) {
                float bv = Bs[(tx + 16*j)*17 + kk];
                acc0[j] += a0 * bv;
                acc1[j] += a1 * bv;
            }
        }
        __syncthreads();
        if (has) {
            As[rowA*G2_BK + c2] = aPre.x;  As[rowA*G2_BK + c2 + 1] = aPre.y;
            #pragma unroll
            for (int it = 0; it < 7; ++it) {
                int i = tid + it*256;
                if (i < 1600) Bs[(i/16)*17 + (i & 15)] = bPre[it];
            }
            __syncthreads();
        }
    }

    #pragma unroll
    for (int j = 0; j < 7; ++j) {
        int n = tx + 16*j;
        if (n >= H2) continue;
        float al = bn2_s[n];
        float be = b2[n]*al + bn2_t[n];
        int m_a = m0 + ty, m_b = m0 + ty + 16;
        float va = fmaxf(acc0[j]*al + be, 0.f);
        float vb = fmaxf(acc1[j]*al + be, 0.f);
        size_t oa = (m_a < NB) ? ((size_t)m_a*H2 + n) : ((size_t)NB*H2 + (size_t)(m_a - NB)*H2 + n);
        size_t ob = (m_b < NB) ? ((size_t)m_b*H2 + n) : ((size_t)NB*H2 + (size_t)(m_b - NB)*H2 + n);
        out[oa] = va;
        out[ob] = vb;
    }
}

// ---------------- Drug encoder v2: no weight staging, 2 CTAs/SM ----------------
#define XPAD 79
#define HPAD 201
#define DSM_XS     0
#define DSM_AGG    (DSM_XS    + NPG*XPAD)      // 5056
#define DSM_H      (DSM_AGG   + NPG*XPAD)      // 10112
#define DSM_TW     (DSM_H     + NPG*HPAD)      // 22976
#define DSM_SCORE  (DSM_TW    + DN)            // 23176
#define DSM_FLAG   (DSM_SCORE + NPG)           // 23240
#define DSM_ES     (DSM_FLAG  + NPG)           // 23304
#define DSM_ED     (DSM_ES    + EPG)           // 23432
#define DSM_FLOATS (DSM_ED    + EPG)           // 23560
#define DRUG_SMEM_BYTES (DSM_FLOATS * 4)       // 94240

__global__ __launch_bounds__(256, 2) void drug_kernel(
    const float* __restrict__ drug_x, const int* __restrict__ edge_index,
    const float* __restrict__ topk_w)
{
    extern __shared__ float sm[];
    float* xs    = sm + DSM_XS;
    float* agg   = sm + DSM_AGG;
    float* hsh   = sm + DSM_H;
    float* tw    = sm + DSM_TW;
    float* score = sm + DSM_SCORE;
    int*   flag  = (int*)(sm + DSM_FLAG);
    int*   es    = (int*)(sm + DSM_ES);
    int*   ed    = (int*)(sm + DSM_ED);

    const int g = blockIdx.x;
    const int tid = threadIdx.x;

    for (int i = tid; i < NPG*DD; i += 256) {
        int n = i / DD, d = i - n*DD;
        xs[n*XPAD + d] = drug_x[(size_t)(g*NPG)*DD + i];
        (void)n;
    }
    for (int i = tid; i < NPG*XPAD; i += 256) agg[i] = 0.f;
    if (tid < DN) tw[tid] = topk_w[tid];
    if (tid < EPG) {
        es[tid] = edge_index[g*EPG + tid] - g*NPG;
        ed[tid] = edge_index[ET_TOT + g*EPG + tid] - g*NPG;
    }
    __syncthreads();

    // parallel edge aggregation via smem atomics
    for (int i = tid; i < EPG*DD; i += 256) {
        int e = i / DD, d = i - e*DD;
        atomicAdd(&agg[ed[e]*XPAD + d], xs[es[e]*XPAD + d]);
    }
    __syncthreads();

    // node GEMM: weights broadcast from global (L2-resident)
    const int n = tid & 63;
    const int grp = tid >> 6;          // 0..3
    const int cbase = grp * 50;
    float acc[50];
    #pragma unroll
    for (int j = 0; j < 50; ++j) acc[j] = 0.f;

    const float* ap = &agg[n*XPAD];
    const float* xp = &xs[n*XPAD];
    const float4* wp = g_Wp + grp * 25;
    for (int d = 0; d < DD; ++d) {
        float av = ap[d], xv = xp[d];
        const float4* wrow = wp + d * 100;
        #pragma unroll
        for (int j2 = 0; j2 < 25; ++j2) {
            float4 w = __ldg(&wrow[j2]);
            acc[2*j2]   += av*w.x + xv*w.z;
            acc[2*j2+1] += av*w.y + xv*w.w;
        }
    }
    #pragma unroll
    for (int j = 0; j < 50; ++j) {
        int c = cbase + j;
        hsh[n*HPAD + c] = fmaxf(acc[j]*g_wa[c] + g_wb[c], 0.f);
    }
    __syncthreads();

    // TopK score
    if (tid < NPG) {
        float s = 0.f;
        const float* hp = &hsh[tid*HPAD];
        for (int c = 0; c < DN; ++c) s += hp[c]*tw[c];
        score[tid] = tanhf(s * g_winv);
    }
    __syncthreads();
    if (tid < NPG) {
        float sn = score[tid];
        int r = 0;
        for (int m2 = 0; m2 < NPG; ++m2) {
            float sv = score[m2];
            r += (sv > sn) || (sv == sn && m2 < tid);
        }
        flag[tid] = (r < KTOP) ? 1 : 0;
    }
    __syncthreads();

    // readouts
    if (tid < DN) {
        const int c = tid;
        float mx = -1e30f, sum = 0.f, mxs = -1e30f, sums = 0.f;
        for (int n2 = 0; n2 < NPG; ++n2) {
            float v = hsh[n2*HPAD + c];
            mx = fmaxf(mx, v); sum += v;
            if (flag[n2]) {
                float w = v * score[n2];
                mxs = fmaxf(mxs, w); sums += w;
            }
        }
        g_dx[(size_t)g*400 + c]       = fmaxf(mx + 3.f*mxs, 0.f);
        g_dx[(size_t)g*400 + DN + c]  = fmaxf(sum*(1.f/NPG) + 3.f*(sums*(1.f/KTOP)), 0.f);
    }
}

// ---------------- resp ----------------
__global__ __launch_bounds__(256) void resp_kernel(
    const float* __restrict__ Wp, const float* __restrict__ bp,
    float* __restrict__ out)
{
    const int row = blockIdx.x * 8 + (threadIdx.x >> 5);
    const int lane = threadIdx.x & 31;
    float s = 0.f;
    for (int i = lane; i < 500; i += 32) {
        float z = (i < H2) ? out[(size_t)row*H2 + i] : g_dx[(size_t)row*400 + (i - H2)];
        s += z * Wp[i];
    }
    #pragma unroll
    for (int o = 16; o; o >>= 1) s += __shfl_down_sync(0xffffffffu, s, o);
    if (lane == 0) out[(size_t)2*NB*H2 + row] = s + bp[0];
}

// ============================================================================
extern "C" void kernel_launch(void* const* d_in, const int* in_sizes, int n_in,
                              void* d_out, int out_size)
{
    const float* x1     = (const float*)d_in[0];
    const float* x2     = (const float*)d_in[1];
    const int*   eidx   = (const int*)d_in[4];
    const float* drug_x = (const float*)d_in[5];
    const float* bn0_s  = (const float*)d_in[6];
    const float* bn0_t  = (const float*)d_in[7];
    const float* W1     = (const float*)d_in[8];
    const float* b1     = (const float*)d_in[9];
    const float* bn1_s  = (const float*)d_in[10];
    const float* bn1_t  = (const float*)d_in[11];
    const float* W2     = (const float*)d_in[12];
    const float* b2     = (const float*)d_in[13];
    const float* bn2_s  = (const float*)d_in[14];
    const float* bn2_t  = (const float*)d_in[15];
    const float* Wrel   = (const float*)d_in[16];
    const float* brel   = (const float*)d_in[17];
    const float* Wroot  = (const float*)d_in[18];
    const float* bnd_s  = (const float*)d_in[19];
    const float* bnd_t  = (const float*)d_in[20];
    const float* topk_w = (const float*)d_in[21];
    const float* Wp     = (const float*)d_in[22];
    const float* bp     = (const float*)d_in[23];
    float* out = (float*)d_out;

    cudaFuncSetAttribute(drug_kernel, cudaFuncAttributeMaxDynamicSharedMemorySize, DRUG_SMEM_BYTES);
    cudaFuncSetAttribute(gemm1_mma, cudaFuncAttributeMaxDynamicSharedMemorySize, G1_DSMEM);

    wprep_kernel<<<31, 256>>>(Wrel, Wroot, brel, bnd_s, bnd_t, topk_w);
    const long NT4 = (long)M_TOT * 2000 + (long)H1 * 2000;
    prep_kernel<<<(int)((NT4 + 255) / 256), 256>>>(x1, x2, W1, bn0_s, bn0_t);
    gemm1_mma<<<dim3(8, 16), 512, G1_DSMEM>>>(b1, bn1_s, bn1_t);
    gemm2_kernel<<<M_TOT / 32, 256>>>(W2, b2, bn2_s, bn2_t, out);
    drug_kernel<<<NG, 256, DRUG_SMEM_BYTES>>>(drug_x, eidx, topk_w);
    resp_kernel<<<NG / 8, 256>>>(Wp, bp, out);
}

// round 6
// speedup vs baseline: 2.2500x; 1.1398x over previous
#include <cuda_runtime.h>
#include <cuda_bf16.h>
#include <math.h>
#include <stdint.h>

#define NB      2048
#define EXPR    8000
#define H1      1024
#define H2      100
#define M_TOT   4096
#define DD      78
#define DN      200
#define NPG     64
#define EPG     128
#define NG      2048
#define ET_TOT  262144
#define KTOP    52

__device__ float g_h1[M_TOT * H1];
__device__ float g_dx[NG * 400];
__device__ __nv_bfloat16 g_Ahi[(size_t)M_TOT * EXPR];
__device__ __nv_bfloat16 g_Alo[(size_t)M_TOT * EXPR];
__device__ __nv_bfloat16 g_Bhi[(size_t)H1 * EXPR];
__device__ __nv_bfloat16 g_Blo[(size_t)H1 * EXPR];
__device__ float4 g_WpT[DD * 104];
__device__ float g_wa2[208], g_wb2[208];
__device__ float g_tw[DN];
__device__ float g_winv;

__device__ __forceinline__ unsigned smem_u32(const void* p) {
    unsigned a;
    asm("{ .reg .u64 t; cvta.to.shared.u64 t, %1; cvt.u32.u64 %0, t; }" : "=r"(a) : "l"(p));
    return a;
}
__device__ __forceinline__ void cpa16(unsigned s, const void* g) {
    asm volatile("cp.async.cg.shared.global [%0], [%1], 16;" :: "r"(s), "l"(g));
}
__device__ __forceinline__ void cpa_commit() { asm volatile("cp.async.commit_group;" ::: "memory"); }
template<int N> __device__ __forceinline__ void cpa_wait() {
    asm volatile("cp.async.wait_group %0;" :: "n"(N) : "memory");
}
__device__ __forceinline__ void ldmx4(unsigned* r, unsigned addr) {
    asm volatile("ldmatrix.sync.aligned.m8n8.x4.shared.b16 {%0,%1,%2,%3}, [%4];"
        : "=r"(r[0]), "=r"(r[1]), "=r"(r[2]), "=r"(r[3]) : "r"(addr));
}
__device__ __forceinline__ void mma16816(float* d, const unsigned* a, const unsigned* b) {
    asm volatile("mma.sync.aligned.m16n8k16.row.col.f32.bf16.bf16.f32 "
        "{%0,%1,%2,%3}, {%4,%5,%6,%7}, {%8,%9}, {%0,%1,%2,%3};"
        : "+f"(d[0]), "+f"(d[1]), "+f"(d[2]), "+f"(d[3])
        : "r"(a[0]), "r"(a[1]), "r"(a[2]), "r"(a[3]), "r"(b[0]), "r"(b[1]));
}

__device__ __forceinline__ void split4(__nv_bfloat16* hi, __nv_bfloat16* lo, float4 v) {
    __nv_bfloat16 h0=__float2bfloat16_rn(v.x), h1=__float2bfloat16_rn(v.y);
    __nv_bfloat16 h2=__float2bfloat16_rn(v.z), h3=__float2bfloat16_rn(v.w);
    union { __nv_bfloat16 b[4]; uint2 u; } H, L;
    H.b[0]=h0; H.b[1]=h1; H.b[2]=h2; H.b[3]=h3;
    L.b[0]=__float2bfloat16_rn(v.x-__bfloat162float(h0));
    L.b[1]=__float2bfloat16_rn(v.y-__bfloat162float(h1));
    L.b[2]=__float2bfloat16_rn(v.z-__bfloat162float(h2));
    L.b[3]=__float2bfloat16_rn(v.w-__bfloat162float(h3));
    *(uint2*)hi = H.u;  *(uint2*)lo = L.u;
}

__global__ __launch_bounds__(256) void prep_kernel(
    const float* __restrict__ x1, const float* __restrict__ x2,
    const float* __restrict__ W1,
    const float* __restrict__ bn0_s, const float* __restrict__ bn0_t)
{
    const long NA = (long)M_TOT * 2000;
    const long NT4 = NA + (long)H1 * 2000;
    long i = (long)blockIdx.x * 256 + threadIdx.x;
    if (i >= NT4) return;
    if (i < NA) {
        int row = (int)(i / 2000), k4 = (int)(i % 2000);
        const float* src = (row < NB) ? (x1 + (size_t)row * EXPR) : (x2 + (size_t)(row - NB) * EXPR);
        float4 v = *(const float4*)(src + k4 * 4);
        float4 s = *(const float4*)(bn0_s + k4 * 4);
        float4 t = *(const float4*)(bn0_t + k4 * 4);
        v.x = v.x*s.x + t.x;  v.y = v.y*s.y + t.y;  v.z = v.z*s.z + t.z;  v.w = v.w*s.w + t.w;
        size_t eo = (size_t)row * EXPR + (size_t)k4 * 4;
        split4(g_Ahi + eo, g_Alo + eo, v);
    } else {
        long j = i - NA;
        int row = (int)(j / 2000), k4 = (int)(j % 2000);
        float4 v = *(const float4*)(W1 + (size_t)row * EXPR + k4 * 4);
        size_t eo = (size_t)row * EXPR + (size_t)k4 * 4;
        split4(g_Bhi + eo, g_Blo + eo, v);
    }
}

__global__ __launch_bounds__(256) void wprep_kernel(
    const float* __restrict__ Wrel, const float* __restrict__ Wroot,
    const float* __restrict__ brel,
    const float* __restrict__ bnd_s, const float* __restrict__ bnd_t,
    const float* __restrict__ topk_w)
{
    int i = blockIdx.x * 256 + threadIdx.x;
    if (i < DD * 104) {
        int d = i / 104, P = i % 104;
        int c0 = 2*P, c1 = 2*P + 1;
        float r0 = (c0 < DN) ? Wrel[c0*DD + d]  : 0.f;
        float r1 = (c1 < DN) ? Wrel[c1*DD + d]  : 0.f;
        float o0 = (c0 < DN) ? Wroot[c0*DD + d] : 0.f;
        float o1 = (c1 < DN) ? Wroot[c1*DD + d] : 0.f;
        g_WpT[i] = make_float4(r0, r1, o0, o1);
    }
    if (i < 208) {
        if (i < DN) {
            float al = bnd_s[i];
            g_wa2[i] = al;
            g_wb2[i] = brel[i]*al + bnd_t[i];
        } else { g_wa2[i] = 0.f; g_wb2[i] = 0.f; }
    }
    if (i < DN) g_tw[i] = topk_w[i];
    if (i == 0) {
        float s = 0.f;
        for (int c = 0; c < DN; ++c) s += topk_w[c]*topk_w[c];
        g_winv = rsqrtf(s);
    }
}

#define KC    32
#define NCH   250
#define AST   40
#define OFF_AH 0
#define OFF_AL 20480
#define OFF_BH 40960
#define OFF_BL 51200
#define STG    61440
#define G1_DSMEM (3 * STG)

__global__ void __launch_bounds__(512, 1) gemm1_mma(
    const float* __restrict__ b1, const float* __restrict__ bn1_s,
    const float* __restrict__ bn1_t)
{
    extern __shared__ char dynsm[];
    __shared__ float s_alpha[128], s_beta[128];
    const unsigned sb = smem_u32(dynsm);
    const int tid = threadIdx.x;
    const int warp = tid >> 5, lane = tid & 31;
    const int m0 = blockIdx.y * 256;
    const int n0 = blockIdx.x * 128;
    const int wm = (warp >> 2) * 64;
    const int wn = (warp & 3) * 32;

    if (tid < 128) {
        float al = bn1_s[n0 + tid];
        s_alpha[tid] = al;
        s_beta[tid]  = b1[n0 + tid] * al + bn1_t[n0 + tid];
    }

    auto load_chunk = [&](int c, int s) {
        const unsigned st = sb + s * STG;
        const long k0 = (long)c * KC;
        #pragma unroll
        for (int t = 0; t < 2; ++t) {
            int i = tid + (t << 9);
            int r = i >> 2, q = i & 3;
            unsigned off = r * 80 + q * 16;
            size_t go = (size_t)(m0 + r) * EXPR + k0 + q * 8;
            cpa16(st + OFF_AH + off, g_Ahi + go);
            cpa16(st + OFF_AL + off, g_Alo + go);
        }
        {
            int r = tid >> 2, q = tid & 3;
            unsigned off = r * 80 + q * 16;
            size_t go = (size_t)(n0 + r) * EXPR + k0 + q * 8;
            cpa16(st + OFF_BH + off, g_Bhi + go);
            cpa16(st + OFF_BL + off, g_Blo + go);
        }
        cpa_commit();
    };

    float acc[4][4][4];
    #pragma unroll
    for (int i = 0; i < 4; ++i)
        #pragma unroll
        for (int j = 0; j < 4; ++j)
            #pragma unroll
            for (int q = 0; q < 4; ++q) acc[i][j][q] = 0.f;

    load_chunk(0, 0);
    load_chunk(1, 1);
    load_chunk(2, 2);

    const int arow = lane & 15;
    const int acol = (lane >> 4) << 3;

    for (int c = 0; c < NCH; ++c) {
        const int s = c - (c / 3) * 3;
        const unsigned aH = sb + s * STG;
        const unsigned aL = aH + OFF_AL;
        const unsigned bH = aH + OFF_BH;
        const unsigned bL = aH + OFF_BL;
        cpa_wait<2>();
        __syncthreads();

        #pragma unroll
        for (int ks = 0; ks < KC; ks += 16) {
            unsigned ah[16], bh[8], u[16];
            #pragma unroll
            for (int i = 0; i < 4; ++i)
                ldmx4(&ah[4*i], aH + ((wm + i*16 + arow) * AST + ks + acol) * 2);
            #pragma unroll
            for (int j2 = 0; j2 < 2; ++j2) {
                unsigned tr[4];
                ldmx4(tr, bH + ((wn + j2*16 + arow) * AST + ks + acol) * 2);
                bh[4*j2 + 0] = tr[0];  bh[4*j2 + 1] = tr[2];
                bh[4*j2 + 2] = tr[1];  bh[4*j2 + 3] = tr[3];
            }
            #pragma unroll
            for (int i = 0; i < 4; ++i)
                #pragma unroll
                for (int j = 0; j < 4; ++j)
                    mma16816(acc[i][j], &ah[4*i], &bh[2*j]);
            #pragma unroll
            for (int j2 = 0; j2 < 2; ++j2) {
                unsigned tr[4];
                ldmx4(tr, bL + ((wn + j2*16 + arow) * AST + ks + acol) * 2);
                u[4*j2 + 0] = tr[0];  u[4*j2 + 1] = tr[2];
                u[4*j2 + 2] = tr[1];  u[4*j2 + 3] = tr[3];
            }
            #pragma unroll
            for (int i = 0; i < 4; ++i)
                #pragma unroll
                for (int j = 0; j < 4; ++j)
                    mma16816(acc[i][j], &ah[4*i], &u[2*j]);
            #pragma unroll
            for (int i = 0; i < 4; ++i)
                ldmx4(&u[4*i], aL + ((wm + i*16 + arow) * AST + ks + acol) * 2);
            #pragma unroll
            for (int i = 0; i < 4; ++i)
                #pragma unroll
                for (int j = 0; j < 4; ++j)
                    mma16816(acc[i][j], &u[4*i], &bh[2*j]);
        }
        __syncthreads();
        if (c + 3 < NCH) load_chunk(c + 3, s);
    }

    const int er = lane >> 2, ec = (lane & 3) * 2;
    #pragma unroll
    for (int i = 0; i < 4; ++i) {
        #pragma unroll
        for (int j = 0; j < 4; ++j) {
            int nl = wn + j*8 + ec;
            float a0 = s_alpha[nl], a1 = s_alpha[nl+1];
            float e0 = s_beta[nl],  e1 = s_beta[nl+1];
            int mg0 = m0 + wm + i*16 + er;
            float2 v0, v1;
            v0.x = fmaxf(acc[i][j][0]*a0 + e0, 0.f);
            v0.y = fmaxf(acc[i][j][1]*a1 + e1, 0.f);
            v1.x = fmaxf(acc[i][j][2]*a0 + e0, 0.f);
            v1.y = fmaxf(acc[i][j][3]*a1 + e1, 0.f);
            *(float2*)&g_h1[(size_t)mg0 * H1 + n0 + nl]       = v0;
            *(float2*)&g_h1[(size_t)(mg0 + 8) * H1 + n0 + nl] = v1;
        }
    }
}

#define G2_BK 16
__global__ __launch_bounds__(256) void gemm2_kernel(
    const float* __restrict__ W2, const float* __restrict__ b2,
    const float* __restrict__ bn2_s, const float* __restrict__ bn2_t,
    float* __restrict__ out)
{
    __shared__ float As[32 * G2_BK];
    __shared__ float Bs[112 * 17];
    const int tid = threadIdx.x;
    const int tx = tid & 15, ty = tid >> 4;
    const int m0 = blockIdx.x * 32;
    const int rowA = tid >> 3, c2 = (tid & 7) * 2;
    const float* pA = g_h1 + (size_t)(m0 + rowA) * H1 + c2;

    float2 aPre;  float bPre[7];
    aPre = *(const float2*)(pA);
    #pragma unroll
    for (int it = 0; it < 7; ++it) {
        int i = tid + it*256;
        if (i < 1600) bPre[it] = W2[(size_t)(i/16) * H1 + (i & 15)];
    }
    As[rowA*G2_BK + c2] = aPre.x;  As[rowA*G2_BK + c2 + 1] = aPre.y;
    #pragma unroll
    for (int it = 0; it < 7; ++it) {
        int i = tid + it*256;
        if (i < 1600) Bs[(i/16)*17 + (i & 15)] = bPre[it];
    }
    __syncthreads();

    float acc0[7], acc1[7];
    #pragma unroll
    for (int j = 0; j < 7; ++j) { acc0[j] = 0.f; acc1[j] = 0.f; }

    const int NT_K = H1 / G2_BK;
    for (int kt = 0; kt < NT_K; ++kt) {
        const bool has = (kt + 1) < NT_K;
        const int k0n = (kt + 1) * G2_BK;
        if (has) {
            aPre = *(const float2*)(pA + k0n);
            #pragma unroll
            for (int it = 0; it < 7; ++it) {
                int i = tid + it*256;
                if (i < 1600) bPre[it] = W2[(size_t)(i/16) * H1 + k0n + (i & 15)];
            }
        }
        #pragma unroll
        for (int kk = 0; kk < G2_BK; ++kk) {
            float a0 = As[ty*G2_BK + kk];
            float a1 = As[(ty + 16)*G2_BK + kk];
            #pragma unroll
            for (int j = 0; j < 7; ++j) {
                float bv = Bs[(tx + 16*j)*17 + kk];
                acc0[j] += a0 * bv;
                acc1[j] += a1 * bv;
            }
        }
        __syncthreads();
        if (has) {
            As[rowA*G2_BK + c2] = aPre.x;  As[rowA*G2_BK + c2 + 1] = aPre.y;
            #pragma unroll
            for (int it = 0; it < 7; ++it) {
                int i = tid + it*256;
                if (i < 1600) Bs[(i/16)*17 + (i & 15)] = bPre[it];
            }
            __syncthreads();
        }
    }

    #pragma unroll
    for (int j = 0; j < 7; ++j) {
        int n = tx + 16*j;
        if (n >= H2) continue;
        float al = bn2_s[n];
        float be = b2[n]*al + bn2_t[n];
        int m_a = m0 + ty, m_b = m0 + ty + 16;
        float va = fmaxf(acc0[j]*al + be, 0.f);
        float vb = fmaxf(acc1[j]*al + be, 0.f);
        size_t oa = (m_a < NB) ? ((size_t)m_a*H2 + n) : ((size_t)NB*H2 + (size_t)(m_a - NB)*H2 + n);
        size_t ob = (m_b < NB) ? ((size_t)m_b*H2 + n) : ((size_t)NB*H2 + (size_t)(m_b - NB)*H2 + n);
        out[oa] = va;
        out[ob] = vb;
    }
}

// ---------------- Drug encoder v3 ----------------
#define XPAD 79
#define HST  209
#define DW_F   (DD * 104 * 4)
#define DWA    (DW_F)
#define DWB    (DWA + 208)
#define DTW    (DWB + 208)
#define DXS    (DTW + 200)
#define DAGG   (DXS + NPG*XPAD)
#define DH     (DAGG + NPG*XPAD)
#define DSC    (DH + NPG*HST)
#define DFLG   (DSC + NPG)
#define DES    (DFLG + NPG)
#define DED    (DES + EPG)
#define DTOT   (DED + EPG)
#define DRUG_SMEM_BYTES (DTOT * 4)
#define DRUG_GRID 148

__global__ __launch_bounds__(512, 1) void drug_kernel(
    const float* __restrict__ drug_x, const int* __restrict__ edge_index)
{
    extern __shared__ float sm[];
    float4* W    = (float4*)sm;
    float* wa    = sm + DWA;
    float* wb    = sm + DWB;
    float* tw    = sm + DTW;
    float* xs    = sm + DXS;
    float* agg   = sm + DAGG;
    float* hsh   = sm + DH;
    float* score = sm + DSC;
    int*   flag  = (int*)(sm + DFLG);
    int*   es    = (int*)(sm + DES);
    int*   ed    = (int*)(sm + DED);

    const int tid = threadIdx.x;
    const int g0 = (int)(((long)blockIdx.x * NG) / DRUG_GRID);
    const int g1 = (int)(((long)(blockIdx.x + 1) * NG) / DRUG_GRID);
    const float winv = g_winv;

    for (int i = tid; i < DD*104; i += 512) W[i] = g_WpT[i];
    if (tid < 208) { wa[tid] = g_wa2[tid]; wb[tid] = g_wb2[tid]; }
    if (tid >= 256 && tid < 256 + DN) tw[tid - 256] = g_tw[tid - 256];
    __syncthreads();

    const int n   = tid & 63;
    const int grp = tid >> 6;
    const float4* wrow0 = W + grp * 13;

    for (int g = g0; g < g1; ++g) {
        const float* gx = drug_x + (size_t)g * NPG * DD;
        for (int i = tid; i < NPG*DD; i += 512) {
            int nn = i / DD, d = i - nn*DD;
            xs[nn*XPAD + d] = gx[i];
        }
        for (int i = tid; i < NPG*XPAD; i += 512) agg[i] = 0.f;
        if (tid < EPG) {
            es[tid] = edge_index[g*EPG + tid] - g*NPG;
            ed[tid] = edge_index[ET_TOT + g*EPG + tid] - g*NPG;
        }
        __syncthreads();

        for (int i = tid; i < EPG*DD; i += 512) {
            int e = i / DD, d = i - e*DD;
            atomicAdd(&agg[ed[e]*XPAD + d], xs[es[e]*XPAD + d]);
        }
        __syncthreads();

        float2 acc[13];
        #pragma unroll
        for (int p = 0; p < 13; ++p) { acc[p].x = 0.f; acc[p].y = 0.f; }
        const float* ap = &agg[n*XPAD];
        const float* xp = &xs[n*XPAD];
        #pragma unroll 2
        for (int d = 0; d < DD; ++d) {
            float av = ap[d], xv = xp[d];
            const float4* wr = wrow0 + d * 104;
            #pragma unroll
            for (int p = 0; p < 13; ++p) {
                float4 w = wr[p];
                acc[p].x += av*w.x + xv*w.z;
                acc[p].y += av*w.y + xv*w.w;
            }
        }
        #pragma unroll
        for (int p = 0; p < 13; ++p) {
            int c = grp*26 + 2*p;
            hsh[n*HST + c]     = fmaxf(acc[p].x*wa[c]   + wb[c],   0.f);
            hsh[n*HST + c + 1] = fmaxf(acc[p].y*wa[c+1] + wb[c+1], 0.f);
        }
        __syncthreads();

        {
            int n2 = tid >> 3, part = tid & 7;
            float s = 0.f;
            const float* hp = &hsh[n2*HST + part*25];
            const float* twp = &tw[part*25];
            #pragma unroll
            for (int c = 0; c < 25; ++c) s += hp[c] * twp[c];
            s += __shfl_xor_sync(0xffffffffu, s, 1);
            s += __shfl_xor_sync(0xffffffffu, s, 2);
            s += __shfl_xor_sync(0xffffffffu, s, 4);
            if (part == 0) score[n2] = tanhf(s * winv);
        }
        __syncthreads();
        if (tid < NPG) {
            float sn = score[tid];
            int r = 0;
            for (int m2 = 0; m2 < NPG; ++m2) {
                float sv = score[m2];
                r += (sv > sn) || (sv == sn && m2 < tid);
            }
            flag[tid] = (r < KTOP) ? 1 : 0;
        }
        __syncthreads();

        if (tid < DN) {
            const int c = tid;
            float mx = -1e30f, sum = 0.f, mxs = -1e30f, sums = 0.f;
            for (int n2 = 0; n2 < NPG; ++n2) {
                float v = hsh[n2*HST + c];
                mx = fmaxf(mx, v); sum += v;
                if (flag[n2]) {
                    float w = v * score[n2];
                    mxs = fmaxf(mxs, w); sums += w;
                }
            }
            g_dx[(size_t)g*400 + c]      = fmaxf(mx + 3.f*mxs, 0.f);
            g_dx[(size_t)g*400 + DN + c] = fmaxf(sum*(1.f/NPG) + 3.f*(sums*(1.f/KTOP)), 0.f);
        }
        __syncthreads();
    }
}

__global__ __launch_bounds__(256) void resp_kernel(
    const float* __restrict__ Wp, const float* __restrict__ bp,
    float* __restrict__ out)
{
    const int row = blockIdx.x * 8 + (threadIdx.x >> 5);
    const int lane = threadIdx.x & 31;
    float s = 0.f;
    for (int i = lane; i < 500; i += 32) {
        float z = (i < H2) ? out[(size_t)row*H2 + i] : g_dx[(size_t)row*400 + (i - H2)];
        s += z * Wp[i];
    }
    #pragma unroll
    for (int o = 16; o; o >>= 1) s += __shfl_down_sync(0xffffffffu, s, o);
    if (lane == 0) out[(size_t)2*NB*H2 + row] = s + bp[0];
}

extern "C" void kernel_launch(void* const* d_in, const int* in_sizes, int n_in,
                              void* d_out, int out_size)
{
    const float* x1     = (const float*)d_in[0];
    const float* x2     = (const float*)d_in[1];
    const int*   eidx   = (const int*)d_in[4];
    const float* drug_x = (const float*)d_in[5];
    const float* bn0_s  = (const float*)d_in[6];
    const float* bn0_t  = (const float*)d_in[7];
    const float* W1     = (const float*)d_in[8];
    const float* b1     = (const float*)d_in[9];
    const float* bn1_s  = (const float*)d_in[10];
    const float* bn1_t  = (const float*)d_in[11];
    const float* W2     = (const float*)d_in[12];
    const float* b2     = (const float*)d_in[13];
    const float* bn2_s  = (const float*)d_in[14];
    const float* bn2_t  = (const float*)d_in[15];
    const float* Wrel   = (const float*)d_in[16];
    const float* brel   = (const float*)d_in[17];
    const float* Wroot  = (const float*)d_in[18];
    const float* bnd_s  = (const float*)d_in[19];
    const float* bnd_t  = (const float*)d_in[20];
    const float* topk_w = (const float*)d_in[21];
    const float* Wp     = (const float*)d_in[22];
    const float* bp     = (const float*)d_in[23];
    float* out = (float*)d_out;

    cudaFuncSetAttribute(drug_kernel, cudaFuncAttributeMaxDynamicSharedMemorySize, DRUG_SMEM_BYTES);
    cudaFuncSetAttribute(gemm1_mma, cudaFuncAttributeMaxDynamicSharedMemorySize, G1_DSMEM);

    wprep_kernel<<<32, 256>>>(Wrel, Wroot, brel, bnd_s, bnd_t, topk_w);
    const long NT4 = (long)M_TOT * 2000 + (long)H1 * 2000;
    prep_kernel<<<(int)((NT4 + 255) / 256), 256>>>(x1, x2, W1, bn0_s, bn0_t);
    gemm1_mma<<<dim3(8, 16), 512, G1_DSMEM>>>(b1, bn1_s, bn1_t);
    gemm2_kernel<<<M_TOT / 32, 256>>>(W2, b2, bn2_s, bn2_t, out);
    drug_kernel<<<DRUG_GRID, 512, DRUG_SMEM_BYTES>>>(drug_x, eidx);
    resp_kernel<<<NG / 8, 256>>>(Wp, bp, out);
}

// round 7
// speedup vs baseline: 2.3747x; 1.0554x over previous
#include <cuda_runtime.h>
#include <cuda_bf16.h>
#include <math.h>
#include <stdint.h>

#define NB      2048
#define EXPR    8000
#define H1      1024
#define H2      100
#define M_TOT   4096
#define DD      78
#define DN      200
#define NPG     64
#define EPG     128
#define NG      2048
#define NT_ALL  131072
#define ET_TOT  262144
#define KTOP    52

__device__ float g_h1[M_TOT * H1];
__device__ float g_dx[NG * 400];
__device__ __nv_bfloat16 g_Ahi[(size_t)M_TOT * EXPR];
__device__ __nv_bfloat16 g_Alo[(size_t)M_TOT * EXPR];
__device__ __nv_bfloat16 g_Bhi[(size_t)H1 * EXPR];
__device__ __nv_bfloat16 g_Blo[(size_t)H1 * EXPR];
__device__ __nv_bfloat16 g_dxhi[(size_t)NT_ALL * 80];
__device__ __nv_bfloat16 g_dxlo[(size_t)NT_ALL * 80];
__device__ __nv_bfloat16 g_wxhi[400 * 80];
__device__ __nv_bfloat16 g_wxlo[400 * 80];
__device__ float g_xl[(size_t)NT_ALL * 400];    // [node][0:200]=x@Wrel^T, [200:400]=x@Wroot^T
__device__ float g_wa2[DN], g_wb2[DN];
__device__ float g_tw[DN];
__device__ float g_winv;

__device__ __forceinline__ unsigned smem_u32(const void* p) {
    unsigned a;
    asm("{ .reg .u64 t; cvta.to.shared.u64 t, %1; cvt.u32.u64 %0, t; }" : "=r"(a) : "l"(p));
    return a;
}
__device__ __forceinline__ void cpa16(unsigned s, const void* g) {
    asm volatile("cp.async.cg.shared.global [%0], [%1], 16;" :: "r"(s), "l"(g));
}
__device__ __forceinline__ void cpa_commit() { asm volatile("cp.async.commit_group;" ::: "memory"); }
template<int N> __device__ __forceinline__ void cpa_wait() {
    asm volatile("cp.async.wait_group %0;" :: "n"(N) : "memory");
}
__device__ __forceinline__ void ldmx4(unsigned* r, unsigned addr) {
    asm volatile("ldmatrix.sync.aligned.m8n8.x4.shared.b16 {%0,%1,%2,%3}, [%4];"
        : "=r"(r[0]), "=r"(r[1]), "=r"(r[2]), "=r"(r[3]) : "r"(addr));
}
__device__ __forceinline__ void mma16816(float* d, const unsigned* a, const unsigned* b) {
    asm volatile("mma.sync.aligned.m16n8k16.row.col.f32.bf16.bf16.f32 "
        "{%0,%1,%2,%3}, {%4,%5,%6,%7}, {%8,%9}, {%0,%1,%2,%3};"
        : "+f"(d[0]), "+f"(d[1]), "+f"(d[2]), "+f"(d[3])
        : "r"(a[0]), "r"(a[1]), "r"(a[2]), "r"(a[3]), "r"(b[0]), "r"(b[1]));
}

__device__ __forceinline__ void split4(__nv_bfloat16* hi, __nv_bfloat16* lo, float4 v) {
    __nv_bfloat16 h0=__float2bfloat16_rn(v.x), h1=__float2bfloat16_rn(v.y);
    __nv_bfloat16 h2=__float2bfloat16_rn(v.z), h3=__float2bfloat16_rn(v.w);
    union { __nv_bfloat16 b[4]; uint2 u; } H, L;
    H.b[0]=h0; H.b[1]=h1; H.b[2]=h2; H.b[3]=h3;
    L.b[0]=__float2bfloat16_rn(v.x-__bfloat162float(h0));
    L.b[1]=__float2bfloat16_rn(v.y-__bfloat162float(h1));
    L.b[2]=__float2bfloat16_rn(v.z-__bfloat162float(h2));
    L.b[3]=__float2bfloat16_rn(v.w-__bfloat162float(h3));
    *(uint2*)hi = H.u;  *(uint2*)lo = L.u;
}
__device__ __forceinline__ void split2(__nv_bfloat16* hi, __nv_bfloat16* lo, float a, float b) {
    __nv_bfloat16 h0=__float2bfloat16_rn(a), h1=__float2bfloat16_rn(b);
    union { __nv_bfloat16 v[2]; unsigned u; } H, L;
    H.v[0]=h0; H.v[1]=h1;
    L.v[0]=__float2bfloat16_rn(a-__bfloat162float(h0));
    L.v[1]=__float2bfloat16_rn(b-__bfloat162float(h1));
    *(unsigned*)hi = H.u;  *(unsigned*)lo = L.u;
}

// ---------------- prep: expression inputs + W1, bf16 hi/lo ----------------
__global__ __launch_bounds__(256) void prep_kernel(
    const float* __restrict__ x1, const float* __restrict__ x2,
    const float* __restrict__ W1,
    const float* __restrict__ bn0_s, const float* __restrict__ bn0_t)
{
    const long NA = (long)M_TOT * 2000;
    const long NT4 = NA + (long)H1 * 2000;
    long i = (long)blockIdx.x * 256 + threadIdx.x;
    if (i >= NT4) return;
    if (i < NA) {
        int row = (int)(i / 2000), k4 = (int)(i % 2000);
        const float* src = (row < NB) ? (x1 + (size_t)row * EXPR) : (x2 + (size_t)(row - NB) * EXPR);
        float4 v = *(const float4*)(src + k4 * 4);
        float4 s = *(const float4*)(bn0_s + k4 * 4);
        float4 t = *(const float4*)(bn0_t + k4 * 4);
        v.x = v.x*s.x + t.x;  v.y = v.y*s.y + t.y;  v.z = v.z*s.z + t.z;  v.w = v.w*s.w + t.w;
        size_t eo = (size_t)row * EXPR + (size_t)k4 * 4;
        split4(g_Ahi + eo, g_Alo + eo, v);
    } else {
        long j = i - NA;
        int row = (int)(j / 2000), k4 = (int)(j % 2000);
        float4 v = *(const float4*)(W1 + (size_t)row * EXPR + k4 * 4);
        size_t eo = (size_t)row * EXPR + (size_t)k4 * 4;
        split4(g_Bhi + eo, g_Blo + eo, v);
    }
}

// ---------------- prep2: drug_x -> bf16 hi/lo, K padded 78->80 ----------------
__global__ __launch_bounds__(256) void prep2_kernel(const float* __restrict__ dx)
{
    long i = (long)blockIdx.x * 256 + threadIdx.x;   // pair index
    if (i >= (long)NT_ALL * 40) return;
    int n = (int)(i / 40), kp = (int)(i % 40);
    int k0 = 2 * kp;
    float a = (k0     < DD) ? dx[(size_t)n * DD + k0]     : 0.f;
    float b = (k0 + 1 < DD) ? dx[(size_t)n * DD + k0 + 1] : 0.f;
    size_t eo = (size_t)n * 80 + k0;
    split2(g_dxhi + eo, g_dxlo + eo, a, b);
}

// ---------------- wprep: concat [Wrel|Wroot] -> [400][80] bf16 hi/lo + folded bn ----------------
__global__ __launch_bounds__(256) void wprep_kernel(
    const float* __restrict__ Wrel, const float* __restrict__ Wroot,
    const float* __restrict__ brel,
    const float* __restrict__ bnd_s, const float* __restrict__ bnd_t,
    const float* __restrict__ topk_w)
{
    int i = blockIdx.x * 256 + threadIdx.x;   // pair index over 400*40
    if (i < 400 * 40) {
        int n = i / 40, kp = i % 40;
        int k0 = 2 * kp;
        float a = 0.f, b = 0.f;
        if (k0 < DD)     a = (n < DN) ? Wrel[n*DD + k0]     : Wroot[(n-DN)*DD + k0];
        if (k0 + 1 < DD) b = (n < DN) ? Wrel[n*DD + k0 + 1] : Wroot[(n-DN)*DD + k0 + 1];
        split2(g_wxhi + n*80 + k0, g_wxlo + n*80 + k0, a, b);
    }
    if (i < DN) {
        float al = bnd_s[i];
        g_wa2[i] = al;
        g_wb2[i] = brel[i]*al + bnd_t[i];
        g_tw[i]  = topk_w[i];
    }
    if (i == 0) {
        float s = 0.f;
        for (int c = 0; c < DN; ++c) s += topk_w[c]*topk_w[c];
        g_winv = rsqrtf(s);
    }
}

// ---------------- GEMM1 via mma.sync (bf16 3-way split) ----------------
#define KC    32
#define NCH   250
#define AST   40
#define OFF_AH 0
#define OFF_AL 20480
#define OFF_BH 40960
#define OFF_BL 51200
#define STG    61440
#define G1_DSMEM (3 * STG)

__global__ void __launch_bounds__(512, 1) gemm1_mma(
    const float* __restrict__ b1, const float* __restrict__ bn1_s,
    const float* __restrict__ bn1_t)
{
    extern __shared__ char dynsm[];
    __shared__ float s_alpha[128], s_beta[128];
    const unsigned sb = smem_u32(dynsm);
    const int tid = threadIdx.x;
    const int warp = tid >> 5, lane = tid & 31;
    const int m0 = blockIdx.y * 256;
    const int n0 = blockIdx.x * 128;
    const int wm = (warp >> 2) * 64;
    const int wn = (warp & 3) * 32;

    if (tid < 128) {
        float al = bn1_s[n0 + tid];
        s_alpha[tid] = al;
        s_beta[tid]  = b1[n0 + tid] * al + bn1_t[n0 + tid];
    }

    auto load_chunk = [&](int c, int s) {
        const unsigned st = sb + s * STG;
        const long k0 = (long)c * KC;
        #pragma unroll
        for (int t = 0; t < 2; ++t) {
            int i = tid + (t << 9);
            int r = i >> 2, q = i & 3;
            unsigned off = r * 80 + q * 16;
            size_t go = (size_t)(m0 + r) * EXPR + k0 + q * 8;
            cpa16(st + OFF_AH + off, g_Ahi + go);
            cpa16(st + OFF_AL + off, g_Alo + go);
        }
        {
            int r = tid >> 2, q = tid & 3;
            unsigned off = r * 80 + q * 16;
            size_t go = (size_t)(n0 + r) * EXPR + k0 + q * 8;
            cpa16(st + OFF_BH + off, g_Bhi + go);
            cpa16(st + OFF_BL + off, g_Blo + go);
        }
        cpa_commit();
    };

    float acc[4][4][4];
    #pragma unroll
    for (int i = 0; i < 4; ++i)
        #pragma unroll
        for (int j = 0; j < 4; ++j)
            #pragma unroll
            for (int q = 0; q < 4; ++q) acc[i][j][q] = 0.f;

    load_chunk(0, 0);
    load_chunk(1, 1);
    load_chunk(2, 2);

    const int arow = lane & 15;
    const int acol = (lane >> 4) << 3;

    for (int c = 0; c < NCH; ++c) {
        const int s = c - (c / 3) * 3;
        const unsigned aH = sb + s * STG;
        const unsigned aL = aH + OFF_AL;
        const unsigned bH = aH + OFF_BH;
        const unsigned bL = aH + OFF_BL;
        cpa_wait<2>();
        __syncthreads();

        #pragma unroll
        for (int ks = 0; ks < KC; ks += 16) {
            unsigned ah[16], bh[8], u[16];
            #pragma unroll
            for (int i = 0; i < 4; ++i)
                ldmx4(&ah[4*i], aH + ((wm + i*16 + arow) * AST + ks + acol) * 2);
            #pragma unroll
            for (int j2 = 0; j2 < 2; ++j2) {
                unsigned tr[4];
                ldmx4(tr, bH + ((wn + j2*16 + arow) * AST + ks + acol) * 2);
                bh[4*j2 + 0] = tr[0];  bh[4*j2 + 1] = tr[2];
                bh[4*j2 + 2] = tr[1];  bh[4*j2 + 3] = tr[3];
            }
            #pragma unroll
            for (int i = 0; i < 4; ++i)
                #pragma unroll
                for (int j = 0; j < 4; ++j)
                    mma16816(acc[i][j], &ah[4*i], &bh[2*j]);
            #pragma unroll
            for (int j2 = 0; j2 < 2; ++j2) {
                unsigned tr[4];
                ldmx4(tr, bL + ((wn + j2*16 + arow) * AST + ks + acol) * 2);
                u[4*j2 + 0] = tr[0];  u[4*j2 + 1] = tr[2];
                u[4*j2 + 2] = tr[1];  u[4*j2 + 3] = tr[3];
            }
            #pragma unroll
            for (int i = 0; i < 4; ++i)
                #pragma unroll
                for (int j = 0; j < 4; ++j)
                    mma16816(acc[i][j], &ah[4*i], &u[2*j]);
            #pragma unroll
            for (int i = 0; i < 4; ++i)
                ldmx4(&u[4*i], aL + ((wm + i*16 + arow) * AST + ks + acol) * 2);
            #pragma unroll
            for (int i = 0; i < 4; ++i)
                #pragma unroll
                for (int j = 0; j < 4; ++j)
                    mma16816(acc[i][j], &u[4*i], &bh[2*j]);
        }
        __syncthreads();
        if (c + 3 < NCH) load_chunk(c + 3, s);
    }

    const int er = lane >> 2, ec = (lane & 3) * 2;
    #pragma unroll
    for (int i = 0; i < 4; ++i) {
        #pragma unroll
        for (int j = 0; j < 4; ++j) {
            int nl = wn + j*8 + ec;
            float a0 = s_alpha[nl], a1 = s_alpha[nl+1];
            float e0 = s_beta[nl],  e1 = s_beta[nl+1];
            int mg0 = m0 + wm + i*16 + er;
            float2 v0, v1;
            v0.x = fmaxf(acc[i][j][0]*a0 + e0, 0.f);
            v0.y = fmaxf(acc[i][j][1]*a1 + e1, 0.f);
            v1.x = fmaxf(acc[i][j][2]*a0 + e0, 0.f);
            v1.y = fmaxf(acc[i][j][3]*a1 + e1, 0.f);
            *(float2*)&g_h1[(size_t)mg0 * H1 + n0 + nl]       = v0;
            *(float2*)&g_h1[(size_t)(mg0 + 8) * H1 + n0 + nl] = v1;
        }
    }
}

// ---------------- XL GEMM: g_xl = drug_x @ [Wrel|Wroot]^T (bf16 3-split) ----------------
// M=131072 (tiles 128), N=400 (tiles 80), K=80 (single block, 5 ksteps)
#define XAST 88
#define XOFF_AH 0
#define XOFF_AL 22528
#define XOFF_BH 45056
#define XOFF_BL 59136
#define XL_DSMEM 73216

__global__ void __launch_bounds__(256, 1) xl_gemm()
{
    extern __shared__ char dynsm[];
    const unsigned sb = smem_u32(dynsm);
    const int tid = threadIdx.x;
    const int warp = tid >> 5, lane = tid & 31;
    const int m0 = blockIdx.y * 128;
    const int n0 = blockIdx.x * 80;

    // load A tile: 128 rows x 80 cols bf16 (10 x 16B chunks per row)
    #pragma unroll
    for (int t = 0; t < 5; ++t) {
        int i = tid + t * 256;            // 0..1279
        int r = i / 10, q = i - r * 10;
        unsigned off = r * 176 + q * 16;
        size_t go = (size_t)(m0 + r) * 80 + q * 8;
        cpa16(sb + XOFF_AH + off, g_dxhi + go);
        cpa16(sb + XOFF_AL + off, g_dxlo + go);
    }
    // load B tile: 80 rows x 80 cols
    #pragma unroll
    for (int t = 0; t < 4; ++t) {
        int i = tid + t * 256;
        if (i < 800) {
            int r = i / 10, q = i - r * 10;
            unsigned off = r * 176 + q * 16;
            size_t go = (size_t)(n0 + r) * 80 + q * 8;
            cpa16(sb + XOFF_BH + off, g_wxhi + go);
            cpa16(sb + XOFF_BL + off, g_wxlo + go);
        }
    }
    cpa_commit();
    cpa_wait<0>();
    __syncthreads();

    float acc[10][4];
    #pragma unroll
    for (int j = 0; j < 10; ++j)
        #pragma unroll
        for (int q = 0; q < 4; ++q) acc[j][q] = 0.f;

    const int arow = lane & 15;
    const int acol = (lane >> 4) << 3;
    const unsigned aH = sb + XOFF_AH, aL = sb + XOFF_AL;
    const unsigned bH = sb + XOFF_BH, bL = sb + XOFF_BL;

    #pragma unroll
    for (int ks = 0; ks < 80; ks += 16) {
        unsigned ah[4], al[4], bh[20], bl[20];
        ldmx4(ah, aH + ((warp*16 + arow) * XAST + ks + acol) * 2);
        ldmx4(al, aL + ((warp*16 + arow) * XAST + ks + acol) * 2);
        #pragma unroll
        for (int jb = 0; jb < 5; ++jb) {
            unsigned tr[4];
            ldmx4(tr, bH + ((jb*16 + arow) * XAST + ks + acol) * 2);
            bh[4*jb+0] = tr[0];  bh[4*jb+1] = tr[2];
            bh[4*jb+2] = tr[1];  bh[4*jb+3] = tr[3];
            ldmx4(tr, bL + ((jb*16 + arow) * XAST + ks + acol) * 2);
            bl[4*jb+0] = tr[0];  bl[4*jb+1] = tr[2];
            bl[4*jb+2] = tr[1];  bl[4*jb+3] = tr[3];
        }
        #pragma unroll
        for (int j = 0; j < 10; ++j) {
            mma16816(acc[j], ah, &bh[2*j]);
            mma16816(acc[j], ah, &bl[2*j]);
            mma16816(acc[j], al, &bh[2*j]);
        }
    }

    const int er = lane >> 2, ec = (lane & 3) * 2;
    const int grow = m0 + warp*16 + er;
    #pragma unroll
    for (int j = 0; j < 10; ++j) {
        int gc = n0 + 8*j + ec;
        *(float2*)&g_xl[(size_t)grow * 400 + gc]       = make_float2(acc[j][0], acc[j][1]);
        *(float2*)&g_xl[(size_t)(grow + 8) * 400 + gc] = make_float2(acc[j][2], acc[j][3]);
    }
}

// ---------------- GEMM2 (unchanged) ----------------
#define G2_BK 16
__global__ __launch_bounds__(256) void gemm2_kernel(
    const float* __restrict__ W2, const float* __restrict__ b2,
    const float* __restrict__ bn2_s, const float* __restrict__ bn2_t,
    float* __restrict__ out)
{
    __shared__ float As[32 * G2_BK];
    __shared__ float Bs[112 * 17];
    const int tid = threadIdx.x;
    const int tx = tid & 15, ty = tid >> 4;
    const int m0 = blockIdx.x * 32;
    const int rowA = tid >> 3, c2 = (tid & 7) * 2;
    const float* pA = g_h1 + (size_t)(m0 + rowA) * H1 + c2;

    float2 aPre;  float bPre[7];
    aPre = *(const float2*)(pA);
    #pragma unroll
    for (int it = 0; it < 7; ++it) {
        int i = tid + it*256;
        if (i < 1600) bPre[it] = W2[(size_t)(i/16) * H1 + (i & 15)];
    }
    As[rowA*G2_BK + c2] = aPre.x;  As[rowA*G2_BK + c2 + 1] = aPre.y;
    #pragma unroll
    for (int it = 0; it < 7; ++it) {
        int i = tid + it*256;
        if (i < 1600) Bs[(i/16)*17 + (i & 15)] = bPre[it];
    }
    __syncthreads();

    float acc0[7], acc1[7];
    #pragma unroll
    for (int j = 0; j < 7; ++j) { acc0[j] = 0.f; acc1[j] = 0.f; }

    const int NT_K = H1 / G2_BK;
    for (int kt = 0; kt < NT_K; ++kt) {
        const bool has = (kt + 1) < NT_K;
        const int k0n = (kt + 1) * G2_BK;
        if (has) {
            aPre = *(const float2*)(pA + k0n);
            #pragma unroll
            for (int it = 0; it < 7; ++it) {
                int i = tid + it*256;
                if (i < 1600) bPre[it] = W2[(size_t)(i/16) * H1 + k0n + (i & 15)];
            }
        }
        #pragma unroll
        for (int kk = 0; kk < G2_BK; ++kk) {
            float a0 = As[ty*G2_BK + kk];
            float a1 = As[(ty + 16)*G2_BK + kk];
            #pragma unroll
            for (int j = 0; j < 7; ++j) {
                float bv = Bs[(tx + 16*j)*17 + kk];
                acc0[j] += a0 * bv;
                acc1[j] += a1 * bv;
            }
        }
        __syncthreads();
        if (has) {
            As[rowA*G2_BK + c2] = aPre.x;  As[rowA*G2_BK + c2 + 1] = aPre.y;
            #pragma unroll
            for (int it = 0; it < 7; ++it) {
                int i = tid + it*256;
                if (i < 1600) Bs[(i/16)*17 + (i & 15)] = bPre[it];
            }
            __syncthreads();
        }
    }

    #pragma unroll
    for (int j = 0; j < 7; ++j) {
        int n = tx + 16*j;
        if (n >= H2) continue;
        float al = bn2_s[n];
        float be = b2[n]*al + bn2_t[n];
        int m_a = m0 + ty, m_b = m0 + ty + 16;
        float va = fmaxf(acc0[j]*al + be, 0.f);
        float vb = fmaxf(acc1[j]*al + be, 0.f);
        size_t oa = (m_a < NB) ? ((size_t)m_a*H2 + n) : ((size_t)NB*H2 + (size_t)(m_a - NB)*H2 + n);
        size_t ob = (m_b < NB) ? ((size_t)m_b*H2 + n) : ((size_t)NB*H2 + (size_t)(m_b - NB)*H2 + n);
        out[oa] = va;
        out[ob] = vb;
    }
}

// ---------------- Drug encoder v5: no GEMM, aggregate precomputed XL ----------------
#define VXL 201
#define VH  209
#define OXL 0
#define OH  12864
#define OWA 26240
#define OWB 26440
#define OTW 26640
#define OSC 26840
#define OFL 26904
#define OES 26968
#define OED 27096
#define OCN 27224
#define OST 27288
#define OCU 27353
#define OLS 27417
#define DTOT 27545
#define DRUG_SMEM_BYTES (DTOT * 4)
#define DRUG_GRID 296

__global__ __launch_bounds__(512, 2) void drug_kernel(const int* __restrict__ edge_index)
{
    extern __shared__ float sm[];
    float* xl    = sm + OXL;
    float* hsh   = sm + OH;
    float* wa    = sm + OWA;
    float* wb    = sm + OWB;
    float* tw    = sm + OTW;
    float* score = sm + OSC;
    int*   flag  = (int*)(sm + OFL);
    int*   es    = (int*)(sm + OES);
    int*   ed    = (int*)(sm + OED);
    int*   cnt   = (int*)(sm + OCN);
    int*   start = (int*)(sm + OST);
    int*   cur   = (int*)(sm + OCU);
    int*   list  = (int*)(sm + OLS);

    const int tid = threadIdx.x;
    const int g0 = (int)(((long)blockIdx.x * NG) / DRUG_GRID);
    const int g1 = (int)(((long)(blockIdx.x + 1) * NG) / DRUG_GRID);
    const float winv = g_winv;

    if (tid < DN) { wa[tid] = g_wa2[tid]; wb[tid] = g_wb2[tid]; tw[tid] = g_tw[tid]; }
    __syncthreads();

    const int ni   = tid >> 3;          // node 0..63
    const int part = tid & 7;           // col chunk of 25
    const int c0   = part * 25;

    for (int g = g0; g < g1; ++g) {
        const int base = g * NPG;
        // stage rel-part of xl for this graph
        for (int i = tid; i < NPG * DN; i += 512) {
            int nn = i / DN, c = i - nn * DN;
            xl[nn * VXL + c] = g_xl[(size_t)(base + nn) * 400 + c];
        }
        if (tid < EPG) {
            es[tid] = edge_index[g*EPG + tid] - base;
            ed[tid] = edge_index[ET_TOT + g*EPG + tid] - base;
        }
        if (tid < NPG) cnt[tid] = 0;
        __syncthreads();
        if (tid < EPG) atomicAdd(&cnt[ed[tid]], 1);
        __syncthreads();
        if (tid == 0) {
            int run = 0;
            for (int nn = 0; nn < NPG; ++nn) { start[nn] = run; run += cnt[nn]; }
            start[NPG] = run;
        }
        __syncthreads();
        if (tid < NPG) cur[tid] = start[tid];
        __syncthreads();
        if (tid < EPG) {
            int pos = atomicAdd(&cur[ed[tid]], 1);
            list[pos] = es[tid];
        }
        __syncthreads();

        // h = relu((sum_in xl_rel[src] + xr + brel)*s + t)
        {
            float acc[25];
            const float* xr = g_xl + (size_t)(base + ni) * 400 + DN + c0;
            #pragma unroll
            for (int c = 0; c < 25; ++c) acc[c] = xr[c];
            const int b0 = start[ni], b1 = start[ni + 1];
            for (int e = b0; e < b1; ++e) {
                const float* xp = xl + list[e] * VXL + c0;
                #pragma unroll
                for (int c = 0; c < 25; ++c) acc[c] += xp[c];
            }
            #pragma unroll
            for (int c = 0; c < 25; ++c) {
                int cc = c0 + c;
                hsh[ni * VH + cc] = fmaxf(acc[c] * wa[cc] + wb[cc], 0.f);
            }
        }
        __syncthreads();

        // score
        {
            float s = 0.f;
            const float* hp  = &hsh[ni * VH + c0];
            const float* twp = &tw[c0];
            #pragma unroll
            for (int c = 0; c < 25; ++c) s += hp[c] * twp[c];
            s += __shfl_xor_sync(0xffffffffu, s, 1);
            s += __shfl_xor_sync(0xffffffffu, s, 2);
            s += __shfl_xor_sync(0xffffffffu, s, 4);
            if (part == 0) score[ni] = tanhf(s * winv);
        }
        __syncthreads();
        if (tid < NPG) {
            float sn = score[tid];
            int r = 0;
            for (int m2 = 0; m2 < NPG; ++m2) {
                float sv = score[m2];
                r += (sv > sn) || (sv == sn && m2 < tid);
            }
            flag[tid] = (r < KTOP) ? 1 : 0;
        }
        __syncthreads();
        if (tid < DN) {
            const int c = tid;
            float mx = -1e30f, sum = 0.f, mxs = -1e30f, sums = 0.f;
            for (int n2 = 0; n2 < NPG; ++n2) {
                float v = hsh[n2 * VH + c];
                mx = fmaxf(mx, v); sum += v;
                if (flag[n2]) {
                    float w = v * score[n2];
                    mxs = fmaxf(mxs, w); sums += w;
                }
            }
            g_dx[(size_t)g*400 + c]      = fmaxf(mx + 3.f*mxs, 0.f);
            g_dx[(size_t)g*400 + DN + c] = fmaxf(sum*(1.f/NPG) + 3.f*(sums*(1.f/KTOP)), 0.f);
        }
        __syncthreads();
    }
}

// ---------------- resp ----------------
__global__ __launch_bounds__(256) void resp_kernel(
    const float* __restrict__ Wp, const float* __restrict__ bp,
    float* __restrict__ out)
{
    const int row = blockIdx.x * 8 + (threadIdx.x >> 5);
    const int lane = threadIdx.x & 31;
    float s = 0.f;
    for (int i = lane; i < 500; i += 32) {
        float z = (i < H2) ? out[(size_t)row*H2 + i] : g_dx[(size_t)row*400 + (i - H2)];
        s += z * Wp[i];
    }
    #pragma unroll
    for (int o = 16; o; o >>= 1) s += __shfl_down_sync(0xffffffffu, s, o);
    if (lane == 0) out[(size_t)2*NB*H2 + row] = s + bp[0];
}

extern "C" void kernel_launch(void* const* d_in, const int* in_sizes, int n_in,
                              void* d_out, int out_size)
{
    const float* x1     = (const float*)d_in[0];
    const float* x2     = (const float*)d_in[1];
    const int*   eidx   = (const int*)d_in[4];
    const float* drug_x = (const float*)d_in[5];
    const float* bn0_s  = (const float*)d_in[6];
    const float* bn0_t  = (const float*)d_in[7];
    const float* W1     = (const float*)d_in[8];
    const float* b1     = (const float*)d_in[9];
    const float* bn1_s  = (const float*)d_in[10];
    const float* bn1_t  = (const float*)d_in[11];
    const float* W2     = (const float*)d_in[12];
    const float* b2     = (const float*)d_in[13];
    const float* bn2_s  = (const float*)d_in[14];
    const float* bn2_t  = (const float*)d_in[15];
    const float* Wrel   = (const float*)d_in[16];
    const float* brel   = (const float*)d_in[17];
    const float* Wroot  = (const float*)d_in[18];
    const float* bnd_s  = (const float*)d_in[19];
    const float* bnd_t  = (const float*)d_in[20];
    const float* topk_w = (const float*)d_in[21];
    const float* Wp     = (const float*)d_in[22];
    const float* bp     = (const float*)d_in[23];
    float* out = (float*)d_out;

    cudaFuncSetAttribute(drug_kernel, cudaFuncAttributeMaxDynamicSharedMemorySize, DRUG_SMEM_BYTES);
    cudaFuncSetAttribute(gemm1_mma, cudaFuncAttributeMaxDynamicSharedMemorySize, G1_DSMEM);
    cudaFuncSetAttribute(xl_gemm, cudaFuncAttributeMaxDynamicSharedMemorySize, XL_DSMEM);

    wprep_kernel<<<63, 256>>>(Wrel, Wroot, brel, bnd_s, bnd_t, topk_w);
    const long NT4 = (long)M_TOT * 2000 + (long)H1 * 2000;
    prep_kernel<<<(int)((NT4 + 255) / 256), 256>>>(x1, x2, W1, bn0_s, bn0_t);
    prep2_kernel<<<20480, 256>>>(drug_x);
    gemm1_mma<<<dim3(8, 16), 512, G1_DSMEM>>>(b1, bn1_s, bn1_t);
    xl_gemm<<<dim3(5, 1024), 256, XL_DSMEM>>>();
    gemm2_kernel<<<M_TOT / 32, 256>>>(W2, b2, bn2_s, bn2_t, out);
    drug_kernel<<<DRUG_GRID, 512, DRUG_SMEM_BYTES>>>(eidx);
    resp_kernel<<<NG / 8, 256>>>(Wp, bp, out);
}